// round 12
// baseline (speedup 1.0000x reference)
#include <cuda_runtime.h>
#include <math.h>
#include <stdint.h>

// Problem constants (fixed by the dataset)
#define NN 50000
#define EE 800000

// ---------------- scratch (static device globals; no allocation) ----------
__device__ float g_g1[(size_t)NN * 384];  // [xl1 | xr1 | res1]
__device__ float g_h1[(size_t)NN * 128];
__device__ float g_g2[(size_t)NN * 256];  // [xl2 | xr2]
__device__ float g_h2[(size_t)NN * 128];
__device__ float g_g3[(size_t)NN * 160];  // [xl3:64 | xr3:48 | res3:48]
__device__ float g_w1[100 * 384];
__device__ float g_w2[128 * 256];
__device__ float g_w3[128 * 160];
__device__ float g_att3p[128];
__device__ int g_cnt[NN];
__device__ int g_offs[NN + 1];
__device__ int g_cur[NN];
__device__ int g_csr[EE];
__device__ int g_bsum[256];
__device__ int g_boff[256];
__device__ int g_dhist[1024];
__device__ int g_dcur[1024];
__device__ int g_order[NN];

// ---------------- CSR construction (4 edges/thread for MLP) ----------------
__global__ void hist_kernel(const int* __restrict__ dst, int* __restrict__ cnt, int e) {
    int base = (blockIdx.x * blockDim.x + threadIdx.x) * 4;
#pragma unroll
    for (int q = 0; q < 4; ++q) {
        int i = base + q;
        if (i < e) atomicAdd(&cnt[dst[i]], 1);
    }
}

// Coalesced 3-stage scan: block sums -> scan block sums -> block scans + offset
__global__ void scanA_kernel(const int* __restrict__ cnt, int* __restrict__ bsum, int n) {
    __shared__ int sh[256];
    int t = threadIdx.x;
    int i = blockIdx.x * 256 + t;
    sh[t] = (i < n) ? cnt[i] : 0;
    __syncthreads();
    for (int off = 128; off > 0; off >>= 1) {
        if (t < off) sh[t] += sh[t + off];
        __syncthreads();
    }
    if (t == 0) bsum[blockIdx.x] = sh[0];
}

__global__ void scanB_kernel(const int* __restrict__ bsum, int* __restrict__ boff, int nb) {
    __shared__ int sh[256];
    int t = threadIdx.x;
    int v = (t < nb) ? bsum[t] : 0;
    sh[t] = v;
    __syncthreads();
    for (int off = 1; off < 256; off <<= 1) {
        int u = (t >= off) ? sh[t - off] : 0;
        __syncthreads();
        sh[t] += u;
        __syncthreads();
    }
    if (t < nb) boff[t] = sh[t] - v;  // exclusive
}

__global__ void scanC_kernel(const int* __restrict__ cnt, const int* __restrict__ boff,
                             int* __restrict__ offs, int* __restrict__ cur, int n) {
    __shared__ int sh[256];
    int t = threadIdx.x;
    int i = blockIdx.x * 256 + t;
    int v = (i < n) ? cnt[i] : 0;
    sh[t] = v;
    __syncthreads();
    for (int off = 1; off < 256; off <<= 1) {
        int u = (t >= off) ? sh[t - off] : 0;
        __syncthreads();
        sh[t] += u;
        __syncthreads();
    }
    int o = boff[blockIdx.x] + sh[t] - v;  // exclusive prefix
    if (i <= n) offs[i] = o;               // i == n -> total (pad cnt = 0)
    if (i < n) cur[i] = o;
}

__global__ void scatter_kernel(const int* __restrict__ src, const int* __restrict__ dst,
                               int* __restrict__ cur, int* __restrict__ csr, int e) {
    int base = (blockIdx.x * blockDim.x + threadIdx.x) * 4;
#pragma unroll
    for (int q = 0; q < 4; ++q) {
        int i = base + q;
        if (i < e) {
            int p = atomicAdd(&cur[dst[i]], 1);
            csr[p] = src[i];
        }
    }
}

// ---------------- degree counting-sort (block-uniform GAT scheduling) ------
__global__ void zeroi_kernel(int* __restrict__ a, int m) {
    int t = blockIdx.x * blockDim.x + threadIdx.x;
    if (t < m) a[t] = 0;
}

__global__ void dhist_kernel(const int* __restrict__ cnt, int* __restrict__ dhist, int n) {
    int i = blockIdx.x * blockDim.x + threadIdx.x;
    if (i < n) atomicAdd(&dhist[min(cnt[i], 1023)], 1);
}

__global__ void dscan_kernel(const int* __restrict__ dhist, int* __restrict__ dcur) {
    __shared__ int sh[1024];
    int t = threadIdx.x;
    int v = dhist[t];
    sh[t] = v;
    __syncthreads();
    for (int off = 1; off < 1024; off <<= 1) {
        int u = (t >= off) ? sh[t - off] : 0;
        __syncthreads();
        sh[t] += u;
        __syncthreads();
    }
    dcur[t] = sh[t] - v;  // exclusive
}

__global__ void dscatter_kernel(const int* __restrict__ cnt, int* __restrict__ dcur,
                                int* __restrict__ order, int n) {
    int i = blockIdx.x * blockDim.x + threadIdx.x;
    if (i < n) {
        int p = atomicAdd(&dcur[min(cnt[i], 1023)], 1);
        order[p] = i;
    }
}

// ---------------- weight packing into padded slots (+optional cnt zeroing) -
__global__ void pack3p_kernel(float* __restrict__ dstp,
                              const float* __restrict__ a, const float* __restrict__ b,
                              const float* __restrict__ c, int K,
                              int Ca, int Pa, int Cb, int Pb, int Cc, int Pc,
                              int* __restrict__ zero_buf, int zero_n) {
    if (zero_buf) {
        for (int idx = blockIdx.x * blockDim.x + threadIdx.x; idx < zero_n;
             idx += gridDim.x * blockDim.x)
            zero_buf[idx] = 0;
    }
    int Cp = Pa + Pb + Pc;
    int total = K * Cp;
    for (int idx = blockIdx.x * blockDim.x + threadIdx.x; idx < total;
         idx += gridDim.x * blockDim.x) {
        int k = idx / Cp;
        int col = idx - k * Cp;
        float v = 0.f;
        if (col < Pa) {
            if (col < Ca) v = a[k * Ca + col];
        } else if (col < Pa + Pb) {
            int cc = col - Pa;
            if (cc < Cb) v = b[k * Cb + cc];
        } else {
            int cc = col - Pa - Pb;
            if (cc < Cc) v = c[k * Cc + cc];
        }
        dstp[idx] = v;
    }
}

// ---------------- TF32 tensor-core GEMM with fragment-order smem ----------
__device__ __forceinline__ uint32_t f2tf32(float f) {
    uint32_t u;
    asm("cvt.rna.tf32.f32 %0, %1;" : "=r"(u) : "f"(f));
    return u;
}

__global__ void __launch_bounds__(256, 2)
sgemm_tf32_kernel(const float* __restrict__ A, const float* __restrict__ B,
                  float* __restrict__ C, int M, int N, int K) {
    __shared__ uint32_t Af[8][4][128];   // 16 KB
    __shared__ uint32_t Bf[4][1152];     // 18 KB (lane stride 36)

    const int t = threadIdx.x;
    const int lane = t & 31;
    const int warp = t >> 5;
    const int brow = blockIdx.y * 128;
    const int bcol = blockIdx.x * 128;
    const int wm = (warp >> 1) * 32;
    const int wn = (warp & 1) * 64;
    const int qm = lane >> 2;
    const int qk = lane & 3;

    float acc[2][8][4];
#pragma unroll
    for (int mi = 0; mi < 2; ++mi)
#pragma unroll
        for (int ni = 0; ni < 8; ++ni)
#pragma unroll
            for (int q = 0; q < 4; ++q) acc[mi][ni][q] = 0.f;

    const int a_m0 = t >> 3;
    const int a_kg = t & 7;
    const int b_n0 = (t & 31) * 4;
    const int b_k0 = t >> 5;
    const int a_kt = a_kg >> 1;
    const int a_ik = a_kg & 1;

    for (int k0 = 0; k0 < K; k0 += 32) {
#pragma unroll
        for (int it = 0; it < 4; ++it) {
            int m = a_m0 + 32 * it;
            int grow = brow + m;
            int gk = k0 + a_kg * 4;
            float4 v = make_float4(0.f, 0.f, 0.f, 0.f);
            if (grow < M && gk < K)
                v = *reinterpret_cast<const float4*>(&A[(size_t)grow * K + gk]);
            int mt = m >> 4;
            int qmw = m & 7;
            int idx = ((m >> 3) & 1) + 2 * a_ik;
            uint32_t* dst = &Af[mt][a_kt][0];
            dst[(qmw * 4 + 0) * 4 + idx] = f2tf32(v.x);
            dst[(qmw * 4 + 1) * 4 + idx] = f2tf32(v.y);
            dst[(qmw * 4 + 2) * 4 + idx] = f2tf32(v.z);
            dst[(qmw * 4 + 3) * 4 + idx] = f2tf32(v.w);
        }
#pragma unroll
        for (int it = 0; it < 4; ++it) {
            int kr = b_k0 + 8 * it;
            int gk = k0 + kr;
            int gn = bcol + b_n0;
            float4 v = make_float4(0.f, 0.f, 0.f, 0.f);
            if (gk < K && gn < N)
                v = *reinterpret_cast<const float4*>(&B[(size_t)gk * N + gn]);
            int kt = kr >> 3;
            int qkb = kr & 3;
            int slot = (kr >> 2) & 1;
            uint32_t* dst = &Bf[kt][0];
            float vv[4] = {v.x, v.y, v.z, v.w};
#pragma unroll
            for (int j = 0; j < 4; ++j) {
                int nn = b_n0 + j;
                int nt = nn >> 3;
                int qmb = nn & 7;
                dst[(qmb * 4 + qkb) * 36 + nt * 2 + slot] = f2tf32(vv[j]);
            }
        }
        __syncthreads();

#pragma unroll
        for (int kk = 0; kk < 4; ++kk) {
            uint32_t af[2][4];
            *reinterpret_cast<uint4*>(af[0]) =
                *reinterpret_cast<const uint4*>(&Af[wm >> 4][kk][lane * 4]);
            *reinterpret_cast<uint4*>(af[1]) =
                *reinterpret_cast<const uint4*>(&Af[(wm >> 4) + 1][kk][lane * 4]);
            uint32_t bfv[8][2];
            const uint32_t* bp = &Bf[kk][lane * 36 + (wn >> 2)];
            *reinterpret_cast<uint4*>(&bfv[0][0]) = *reinterpret_cast<const uint4*>(bp);
            *reinterpret_cast<uint4*>(&bfv[2][0]) = *reinterpret_cast<const uint4*>(bp + 4);
            *reinterpret_cast<uint4*>(&bfv[4][0]) = *reinterpret_cast<const uint4*>(bp + 8);
            *reinterpret_cast<uint4*>(&bfv[6][0]) = *reinterpret_cast<const uint4*>(bp + 12);
#pragma unroll
            for (int mi = 0; mi < 2; ++mi)
#pragma unroll
                for (int ni = 0; ni < 8; ++ni) {
                    asm volatile(
                        "mma.sync.aligned.m16n8k8.row.col.f32.tf32.tf32.f32 "
                        "{%0,%1,%2,%3}, {%4,%5,%6,%7}, {%8,%9}, {%0,%1,%2,%3};"
                        : "+f"(acc[mi][ni][0]), "+f"(acc[mi][ni][1]),
                          "+f"(acc[mi][ni][2]), "+f"(acc[mi][ni][3])
                        : "r"(af[mi][0]), "r"(af[mi][1]), "r"(af[mi][2]), "r"(af[mi][3]),
                          "r"(bfv[ni][0]), "r"(bfv[ni][1]));
                }
        }
        __syncthreads();
    }

#pragma unroll
    for (int mi = 0; mi < 2; ++mi) {
#pragma unroll
        for (int ni = 0; ni < 8; ++ni) {
            int r0 = brow + wm + mi * 16 + qm;
            int cc = bcol + wn + ni * 8 + 2 * qk;
            if (cc + 1 < N) {
                if (r0 < M)
                    *reinterpret_cast<float2*>(&C[(size_t)r0 * N + cc]) =
                        make_float2(acc[mi][ni][0], acc[mi][ni][1]);
                if (r0 + 8 < M)
                    *reinterpret_cast<float2*>(&C[(size_t)(r0 + 8) * N + cc]) =
                        make_float2(acc[mi][ni][2], acc[mi][ni][3]);
            } else if (cc < N) {
                if (r0 < M) C[(size_t)r0 * N + cc] = acc[mi][ni][0];
                if (r0 + 8 < M) C[(size_t)(r0 + 8) * N + cc] = acc[mi][ni][2];
            }
        }
    }
}

// ---------------- GATv2 4-head edge kernel: half-warp-paired edges ---------
// Warp w processes node order[w] (degree-sorted for block-uniform runtimes).
__global__ void gat4_kernel(const float* __restrict__ xlr, int ld,
                            const float* __restrict__ att,
                            const float* __restrict__ bias,
                            const float* __restrict__ resid, int ldr,
                            const float* __restrict__ res_b,
                            const float* __restrict__ bn_g, const float* __restrict__ bn_b,
                            const float* __restrict__ bn_m, const float* __restrict__ bn_v,
                            float* __restrict__ out, int do_relu,
                            const int* __restrict__ offs, const int* __restrict__ csr,
                            const int* __restrict__ order, int n) {
    int warp = (blockIdx.x * blockDim.x + threadIdx.x) >> 5;
    int lane = threadIdx.x & 31;
    if (warp >= n) return;
    const int i = order[warp];
    const int half = lane >> 4;
    const int ch = (lane & 15) * 8;

    const float* xrrow = xlr + (size_t)i * ld + 128 + ch;
    const float4 xr0 = *reinterpret_cast<const float4*>(xrrow);
    const float4 xr1 = *reinterpret_cast<const float4*>(xrrow + 4);
    const float4 at0 = *reinterpret_cast<const float4*>(att + ch);
    const float4 at1 = *reinterpret_cast<const float4*>(att + ch + 4);

    float dsum = 0.f;
    float4 acc0 = make_float4(0.f, 0.f, 0.f, 0.f);
    float4 acc1 = make_float4(0.f, 0.f, 0.f, 0.f);

    int e0 = offs[i];
    int deg = offs[i + 1] - e0;
    int tot = deg + 1;          // + implicit self-loop (index deg)
    int npair = (tot + 1) >> 1;

    // prefetch pair 0
    int idx0 = half;
    int s0 = (idx0 < deg) ? csr[e0 + idx0] : i;
    const float* r0p = xlr + (size_t)s0 * ld + ch;
    float4 v0 = *reinterpret_cast<const float4*>(r0p);
    float4 v1 = *reinterpret_cast<const float4*>(r0p + 4);

    for (int k = 0; k < npair; ++k) {
        float4 c0 = v0, c1 = v1;
        bool valid = (2 * k + half) < tot;
        if (k + 1 < npair) {
            int idxn = 2 * (k + 1) + half;
            int sn = (idxn < deg) ? csr[e0 + idxn] : i;
            const float* rn = xlr + (size_t)sn * ld + ch;
            v0 = *reinterpret_cast<const float4*>(rn);
            v1 = *reinterpret_cast<const float4*>(rn + 4);
        }
        float u, p;
        u = c0.x + xr0.x; u = fmaxf(u, 0.2f * u); p = u * at0.x;
        u = c0.y + xr0.y; u = fmaxf(u, 0.2f * u); p = fmaf(u, at0.y, p);
        u = c0.z + xr0.z; u = fmaxf(u, 0.2f * u); p = fmaf(u, at0.z, p);
        u = c0.w + xr0.w; u = fmaxf(u, 0.2f * u); p = fmaf(u, at0.w, p);
        u = c1.x + xr1.x; u = fmaxf(u, 0.2f * u); p = fmaf(u, at1.x, p);
        u = c1.y + xr1.y; u = fmaxf(u, 0.2f * u); p = fmaf(u, at1.y, p);
        u = c1.z + xr1.z; u = fmaxf(u, 0.2f * u); p = fmaf(u, at1.z, p);
        u = c1.w + xr1.w; u = fmaxf(u, 0.2f * u); p = fmaf(u, at1.w, p);
        // reduce over the 4 lanes sharing this head (within the 16-lane half)
        p += __shfl_xor_sync(0xffffffffu, p, 1);
        p += __shfl_xor_sync(0xffffffffu, p, 2);
        float w = valid ? __expf(p) : 0.f;
        dsum += w;
        acc0.x = fmaf(w, c0.x, acc0.x);
        acc0.y = fmaf(w, c0.y, acc0.y);
        acc0.z = fmaf(w, c0.z, acc0.z);
        acc0.w = fmaf(w, c0.w, acc0.w);
        acc1.x = fmaf(w, c1.x, acc1.x);
        acc1.y = fmaf(w, c1.y, acc1.y);
        acc1.z = fmaf(w, c1.z, acc1.z);
        acc1.w = fmaf(w, c1.w, acc1.w);
    }

    // merge the two halves (same channels, different edge subsets)
    dsum += __shfl_xor_sync(0xffffffffu, dsum, 16);
    acc0.x += __shfl_xor_sync(0xffffffffu, acc0.x, 16);
    acc0.y += __shfl_xor_sync(0xffffffffu, acc0.y, 16);
    acc0.z += __shfl_xor_sync(0xffffffffu, acc0.z, 16);
    acc0.w += __shfl_xor_sync(0xffffffffu, acc0.w, 16);
    acc1.x += __shfl_xor_sync(0xffffffffu, acc1.x, 16);
    acc1.y += __shfl_xor_sync(0xffffffffu, acc1.y, 16);
    acc1.z += __shfl_xor_sync(0xffffffffu, acc1.z, 16);
    acc1.w += __shfl_xor_sync(0xffffffffu, acc1.w, 16);

    if (half == 0) {
        float inv = 1.f / dsum;
        float4 bi0 = *reinterpret_cast<const float4*>(bias + ch);
        float4 bi1 = *reinterpret_cast<const float4*>(bias + ch + 4);
        const float* rr = resid + (size_t)i * ldr + ch;
        float4 rs0 = *reinterpret_cast<const float4*>(rr);
        float4 rs1 = *reinterpret_cast<const float4*>(rr + 4);
        float4 o0, o1;
        o0.x = acc0.x * inv + bi0.x + rs0.x;
        o0.y = acc0.y * inv + bi0.y + rs0.y;
        o0.z = acc0.z * inv + bi0.z + rs0.z;
        o0.w = acc0.w * inv + bi0.w + rs0.w;
        o1.x = acc1.x * inv + bi1.x + rs1.x;
        o1.y = acc1.y * inv + bi1.y + rs1.y;
        o1.z = acc1.z * inv + bi1.z + rs1.z;
        o1.w = acc1.w * inv + bi1.w + rs1.w;
        if (res_b) {
            float4 rb0 = *reinterpret_cast<const float4*>(res_b + ch);
            float4 rb1 = *reinterpret_cast<const float4*>(res_b + ch + 4);
            o0.x += rb0.x; o0.y += rb0.y; o0.z += rb0.z; o0.w += rb0.w;
            o1.x += rb1.x; o1.y += rb1.y; o1.z += rb1.z; o1.w += rb1.w;
        }
        float4 g0 = *reinterpret_cast<const float4*>(bn_g + ch);
        float4 g1 = *reinterpret_cast<const float4*>(bn_g + ch + 4);
        float4 bb0 = *reinterpret_cast<const float4*>(bn_b + ch);
        float4 bb1 = *reinterpret_cast<const float4*>(bn_b + ch + 4);
        float4 mm0 = *reinterpret_cast<const float4*>(bn_m + ch);
        float4 mm1 = *reinterpret_cast<const float4*>(bn_m + ch + 4);
        float4 vv0 = *reinterpret_cast<const float4*>(bn_v + ch);
        float4 vv1 = *reinterpret_cast<const float4*>(bn_v + ch + 4);
        o0.x = (o0.x - mm0.x) * rsqrtf(vv0.x + 1e-5f) * g0.x + bb0.x;
        o0.y = (o0.y - mm0.y) * rsqrtf(vv0.y + 1e-5f) * g0.y + bb0.y;
        o0.z = (o0.z - mm0.z) * rsqrtf(vv0.z + 1e-5f) * g0.z + bb0.z;
        o0.w = (o0.w - mm0.w) * rsqrtf(vv0.w + 1e-5f) * g0.w + bb0.w;
        o1.x = (o1.x - mm1.x) * rsqrtf(vv1.x + 1e-5f) * g1.x + bb1.x;
        o1.y = (o1.y - mm1.y) * rsqrtf(vv1.y + 1e-5f) * g1.y + bb1.y;
        o1.z = (o1.z - mm1.z) * rsqrtf(vv1.z + 1e-5f) * g1.z + bb1.z;
        o1.w = (o1.w - mm1.w) * rsqrtf(vv1.w + 1e-5f) * g1.w + bb1.w;
        if (do_relu) {
            o0.x = fmaxf(o0.x, 0.f); o0.y = fmaxf(o0.y, 0.f);
            o0.z = fmaxf(o0.z, 0.f); o0.w = fmaxf(o0.w, 0.f);
            o1.x = fmaxf(o1.x, 0.f); o1.y = fmaxf(o1.y, 0.f);
            o1.z = fmaxf(o1.z, 0.f); o1.w = fmaxf(o1.w, 0.f);
        }
        float* orow = out + (size_t)i * 128 + ch;
        *reinterpret_cast<float4*>(orow) = o0;
        *reinterpret_cast<float4*>(orow + 4) = o1;
    }
}

// ---------------- layer-3 GAT (heads=1, ch=47), padded layout ld=160 -------
__global__ void gat1_kernel(const float* __restrict__ xlr,
                            const float* __restrict__ attp,
                            const float* __restrict__ bias,
                            const float* __restrict__ res_b,
                            const float* __restrict__ bn_g, const float* __restrict__ bn_b,
                            const float* __restrict__ bn_m, const float* __restrict__ bn_v,
                            float* __restrict__ out,
                            const int* __restrict__ offs, const int* __restrict__ csr,
                            const int* __restrict__ order, int n) {
    int warp = (blockIdx.x * blockDim.x + threadIdx.x) >> 5;
    int lane = threadIdx.x & 31;
    if (warp >= n) return;
    const int i = order[warp];
    const int ld = 160;
    const bool act = (lane < 12);

    float4 xrv = make_float4(0.f, 0.f, 0.f, 0.f);
    if (act)
        xrv = *reinterpret_cast<const float4*>(xlr + (size_t)i * ld + 64 + 4 * lane);
    const float4 attv = reinterpret_cast<const float4*>(attp)[lane];

    float d = 0.f;
    float4 acc = make_float4(0.f, 0.f, 0.f, 0.f);

    int e0 = offs[i];
    int deg = offs[i + 1] - e0;

    float4 v = make_float4(0.f, 0.f, 0.f, 0.f);
    {
        int s = (deg > 0) ? csr[e0] : i;
        if (act) v = *reinterpret_cast<const float4*>(xlr + (size_t)s * ld + 4 * lane);
    }

    for (int t = 0; t <= deg; ++t) {
        float4 cur = v;
        if (t < deg) {
            int sn = (t + 1 < deg) ? csr[e0 + t + 1] : i;
            if (act) v = *reinterpret_cast<const float4*>(xlr + (size_t)sn * ld + 4 * lane);
        }
        float ux = cur.x + xrv.x, uy = cur.y + xrv.y,
              uz = cur.z + xrv.z, uw = cur.w + xrv.w;
        ux = fmaxf(ux, 0.2f * ux);
        uy = fmaxf(uy, 0.2f * uy);
        uz = fmaxf(uz, 0.2f * uz);
        uw = fmaxf(uw, 0.2f * uw);
        float p = fmaf(ux, attv.x, fmaf(uy, attv.y, fmaf(uz, attv.z, uw * attv.w)));
#pragma unroll
        for (int off = 16; off > 0; off >>= 1) p += __shfl_xor_sync(0xffffffffu, p, off);
        float w = __expf(p);
        d += w;
        acc.x = fmaf(w, cur.x, acc.x);
        acc.y = fmaf(w, cur.y, acc.y);
        acc.z = fmaf(w, cur.z, acc.z);
        acc.w = fmaf(w, cur.w, acc.w);
    }

    if (act) {
        float inv = 1.f / d;
        const float* resrow = xlr + (size_t)i * ld + 112;
        float a4[4] = {acc.x, acc.y, acc.z, acc.w};
#pragma unroll
        for (int q = 0; q < 4; ++q) {
            int c = 4 * lane + q;
            if (c < 47) {
                float v2 = a4[q] * inv + bias[c] + resrow[c] + res_b[c];
                v2 = (v2 - bn_m[c]) * rsqrtf(bn_v[c] + 1e-5f) * bn_g[c] + bn_b[c];
                out[(size_t)i * 47 + c] = v2;
            }
        }
    }
}

// ---------------- host launch ---------------------------------------------
extern "C" void kernel_launch(void* const* d_in, const int* in_sizes, int n_in,
                              void* d_out, int out_size) {
    const float* x = (const float*)d_in[0];
    const int* ei = (const int*)d_in[1];
    const float* w1_src = (const float*)d_in[2];
    const float* w1_dst = (const float*)d_in[3];
    const float* att1 = (const float*)d_in[4];
    const float* b1 = (const float*)d_in[5];
    const float* bn1_g = (const float*)d_in[6];
    const float* bn1_b = (const float*)d_in[7];
    const float* bn1_m = (const float*)d_in[8];
    const float* bn1_v = (const float*)d_in[9];
    const float* res0_w = (const float*)d_in[10];
    const float* res0_b = (const float*)d_in[11];
    const float* w2_src = (const float*)d_in[12];
    const float* w2_dst = (const float*)d_in[13];
    const float* att2 = (const float*)d_in[14];
    const float* b2 = (const float*)d_in[15];
    const float* bn2_g = (const float*)d_in[16];
    const float* bn2_b = (const float*)d_in[17];
    const float* bn2_m = (const float*)d_in[18];
    const float* bn2_v = (const float*)d_in[19];
    const float* w3_src = (const float*)d_in[20];
    const float* w3_dst = (const float*)d_in[21];
    const float* att3 = (const float*)d_in[22];
    const float* b3 = (const float*)d_in[23];
    const float* bn3_g = (const float*)d_in[24];
    const float* bn3_b = (const float*)d_in[25];
    const float* bn3_m = (const float*)d_in[26];
    const float* bn3_v = (const float*)d_in[27];
    const float* res2_w = (const float*)d_in[28];
    const float* res2_b = (const float*)d_in[29];

    int n = in_sizes[0] / 100;
    int e = in_sizes[1] / 2;
    if (n > NN) n = NN;
    if (e > EE) e = EE;
    const int* srcp = ei;
    const int* dstp = ei + e;

    float *g1, *h1, *g2, *h2, *g3, *w1b, *w2b, *w3b, *att3p;
    int *cnt, *offs, *cur, *csr, *bsum, *boff, *dhist, *dcur, *order;
    cudaGetSymbolAddress((void**)&g1, g_g1);
    cudaGetSymbolAddress((void**)&h1, g_h1);
    cudaGetSymbolAddress((void**)&g2, g_g2);
    cudaGetSymbolAddress((void**)&h2, g_h2);
    cudaGetSymbolAddress((void**)&g3, g_g3);
    cudaGetSymbolAddress((void**)&w1b, g_w1);
    cudaGetSymbolAddress((void**)&w2b, g_w2);
    cudaGetSymbolAddress((void**)&w3b, g_w3);
    cudaGetSymbolAddress((void**)&att3p, g_att3p);
    cudaGetSymbolAddress((void**)&cnt, g_cnt);
    cudaGetSymbolAddress((void**)&offs, g_offs);
    cudaGetSymbolAddress((void**)&cur, g_cur);
    cudaGetSymbolAddress((void**)&csr, g_csr);
    cudaGetSymbolAddress((void**)&bsum, g_bsum);
    cudaGetSymbolAddress((void**)&boff, g_boff);
    cudaGetSymbolAddress((void**)&dhist, g_dhist);
    cudaGetSymbolAddress((void**)&dcur, g_dcur);
    cudaGetSymbolAddress((void**)&order, g_order);

    int gatBlocks = (n + 7) / 8;
    int rowsB = (n + 127) / 128;
    int edgeBlocks = (e + 1023) / 1024;  // 4 edges per thread
    int scanBlocks = (n + 255) / 256;    // 196 for n=50000
    int nodeBlocks = (n + 255) / 256;

    zeroi_kernel<<<4, 256>>>(dhist, 1024);
    pack3p_kernel<<<64, 256>>>(w1b, w1_src, w1_dst, res0_w, 100,
                               128, 128, 128, 128, 128, 128, cnt, n);
    hist_kernel<<<edgeBlocks, 256>>>(dstp, cnt, e);
    scanA_kernel<<<scanBlocks, 256>>>(cnt, bsum, n);
    scanB_kernel<<<1, 256>>>(bsum, boff, scanBlocks);
    scanC_kernel<<<scanBlocks, 256>>>(cnt, boff, offs, cur, n);
    scatter_kernel<<<edgeBlocks, 256>>>(srcp, dstp, cur, csr, e);
    // degree counting-sort -> order[] (block-uniform GAT runtimes)
    dhist_kernel<<<nodeBlocks, 256>>>(cnt, dhist, n);
    dscan_kernel<<<1, 1024>>>(dhist, dcur);
    dscatter_kernel<<<nodeBlocks, 256>>>(cnt, dcur, order, n);

    sgemm_tf32_kernel<<<dim3(3, rowsB), 256>>>(x, w1b, g1, n, 384, 100);

    // ----- layer 1 -----
    gat4_kernel<<<gatBlocks, 256>>>(g1, 384, att1, b1,
                                    g1 + 256, 384, res0_b,
                                    bn1_g, bn1_b, bn1_m, bn1_v,
                                    h1, 1, offs, csr, order, n);

    // ----- layer 2 -----
    pack3p_kernel<<<64, 256>>>(w2b, w2_src, w2_dst, nullptr, 128,
                               128, 128, 128, 128, 0, 0, nullptr, 0);
    sgemm_tf32_kernel<<<dim3(2, rowsB), 256>>>(h1, w2b, g2, n, 256, 128);
    gat4_kernel<<<gatBlocks, 256>>>(g2, 256, att2, b2,
                                    h1, 128, nullptr,
                                    bn2_g, bn2_b, bn2_m, bn2_v,
                                    h2, 1, offs, csr, order, n);

    // ----- layer 3 -----
    pack3p_kernel<<<64, 256>>>(w3b, w3_src, w3_dst, res2_w, 128,
                               47, 64, 47, 48, 47, 48, nullptr, 0);
    pack3p_kernel<<<1, 128>>>(att3p, att3, nullptr, nullptr, 1,
                              47, 128, 0, 0, 0, 0, nullptr, 0);
    sgemm_tf32_kernel<<<dim3(2, rowsB), 256>>>(h2, w3b, g3, n, 160, 128);
    gat1_kernel<<<gatBlocks, 256>>>(g3, att3p, b3, res2_b,
                                    bn3_g, bn3_b, bn3_m, bn3_v,
                                    (float*)d_out, offs, csr, order, n);
}

// round 13
// speedup vs baseline: 1.1405x; 1.1405x over previous
#include <cuda_runtime.h>
#include <math.h>
#include <stdint.h>

// Problem constants (fixed by the dataset)
#define NN 50000
#define EE 800000

// ---------------- scratch (static device globals; no allocation) ----------
__device__ float g_g1[(size_t)NN * 384];  // [xl1 | xr1 | res1]
__device__ float g_h1[(size_t)NN * 128];
__device__ float g_g2[(size_t)NN * 256];  // [xl2 | xr2]
__device__ float g_h2[(size_t)NN * 128];
__device__ float g_g3[(size_t)NN * 160];  // [xl3:64 | xr3:48 | res3:48]
__device__ float g_w1[100 * 384];
__device__ float g_w2[128 * 256];
__device__ float g_w3[128 * 160];
__device__ float g_att3p[128];
__device__ int g_cnt[NN];
__device__ int g_offs[NN + 1];
__device__ int g_cur[NN];
__device__ int g_csr[EE];
__device__ int g_bsum[256];
__device__ int g_boff[256];

// ---------------- fused prep: zero cnt + pack w1/w2/w3 + pad att3 ----------
__global__ void prep_kernel(const float* __restrict__ w1_src, const float* __restrict__ w1_dst,
                            const float* __restrict__ res0_w,
                            const float* __restrict__ w2_src, const float* __restrict__ w2_dst,
                            const float* __restrict__ w3_src, const float* __restrict__ w3_dst,
                            const float* __restrict__ res2_w,
                            const float* __restrict__ att3,
                            float* __restrict__ w1b, float* __restrict__ w2b,
                            float* __restrict__ w3b, float* __restrict__ att3p,
                            int* __restrict__ cnt, int n) {
    const int W1T = 100 * 384;
    const int W2T = 128 * 256;
    const int W3T = 128 * 160;
    int total = n + W1T + W2T + W3T + 128;
    for (int idx = blockIdx.x * blockDim.x + threadIdx.x; idx < total;
         idx += gridDim.x * blockDim.x) {
        int r = idx;
        if (r < n) { cnt[r] = 0; continue; }
        r -= n;
        if (r < W1T) {
            int k = r / 384, col = r - k * 384;
            float v;
            if (col < 128) v = w1_src[k * 128 + col];
            else if (col < 256) v = w1_dst[k * 128 + col - 128];
            else v = res0_w[k * 128 + col - 256];
            w1b[r] = v;
            continue;
        }
        r -= W1T;
        if (r < W2T) {
            int k = r >> 8, col = r & 255;
            w2b[r] = (col < 128) ? w2_src[k * 128 + col] : w2_dst[k * 128 + col - 128];
            continue;
        }
        r -= W2T;
        if (r < W3T) {
            int k = r / 160, col = r - k * 160;
            float v = 0.f;
            if (col < 64) { if (col < 47) v = w3_src[k * 47 + col]; }
            else if (col < 112) { int c = col - 64; if (c < 47) v = w3_dst[k * 47 + c]; }
            else { int c = col - 112; if (c < 47) v = res2_w[k * 47 + c]; }
            w3b[r] = v;
            continue;
        }
        r -= W3T;
        att3p[r] = (r < 47) ? att3[r] : 0.f;
    }
}

// ---------------- CSR construction (4 edges/thread for MLP) ----------------
__global__ void hist_kernel(const int* __restrict__ dst, int* __restrict__ cnt, int e) {
    int base = (blockIdx.x * blockDim.x + threadIdx.x) * 4;
#pragma unroll
    for (int q = 0; q < 4; ++q) {
        int i = base + q;
        if (i < e) atomicAdd(&cnt[dst[i]], 1);
    }
}

__global__ void scanA_kernel(const int* __restrict__ cnt, int* __restrict__ bsum, int n) {
    __shared__ int sh[256];
    int t = threadIdx.x;
    int i = blockIdx.x * 256 + t;
    sh[t] = (i < n) ? cnt[i] : 0;
    __syncthreads();
    for (int off = 128; off > 0; off >>= 1) {
        if (t < off) sh[t] += sh[t + off];
        __syncthreads();
    }
    if (t == 0) bsum[blockIdx.x] = sh[0];
}

__global__ void scanB_kernel(const int* __restrict__ bsum, int* __restrict__ boff, int nb) {
    __shared__ int sh[256];
    int t = threadIdx.x;
    int v = (t < nb) ? bsum[t] : 0;
    sh[t] = v;
    __syncthreads();
    for (int off = 1; off < 256; off <<= 1) {
        int u = (t >= off) ? sh[t - off] : 0;
        __syncthreads();
        sh[t] += u;
        __syncthreads();
    }
    if (t < nb) boff[t] = sh[t] - v;  // exclusive
}

__global__ void scanC_kernel(const int* __restrict__ cnt, const int* __restrict__ boff,
                             int* __restrict__ offs, int* __restrict__ cur, int n) {
    __shared__ int sh[256];
    int t = threadIdx.x;
    int i = blockIdx.x * 256 + t;
    int v = (i < n) ? cnt[i] : 0;
    sh[t] = v;
    __syncthreads();
    for (int off = 1; off < 256; off <<= 1) {
        int u = (t >= off) ? sh[t - off] : 0;
        __syncthreads();
        sh[t] += u;
        __syncthreads();
    }
    int o = boff[blockIdx.x] + sh[t] - v;  // exclusive prefix
    if (i <= n) offs[i] = o;               // i == n -> total (pad cnt = 0)
    if (i < n) cur[i] = o;
}

__global__ void scatter_kernel(const int* __restrict__ src, const int* __restrict__ dst,
                               int* __restrict__ cur, int* __restrict__ csr, int e) {
    int base = (blockIdx.x * blockDim.x + threadIdx.x) * 4;
#pragma unroll
    for (int q = 0; q < 4; ++q) {
        int i = base + q;
        if (i < e) {
            int p = atomicAdd(&cur[dst[i]], 1);
            csr[p] = src[i];
        }
    }
}

// ---------------- TF32 tensor-core GEMM with fragment-order smem ----------
__device__ __forceinline__ uint32_t f2tf32(float f) {
    uint32_t u;
    asm("cvt.rna.tf32.f32 %0, %1;" : "=r"(u) : "f"(f));
    return u;
}

__global__ void __launch_bounds__(256, 2)
sgemm_tf32_kernel(const float* __restrict__ A, const float* __restrict__ B,
                  float* __restrict__ C, int M, int N, int K) {
    __shared__ uint32_t Af[8][4][128];   // 16 KB
    __shared__ uint32_t Bf[4][1152];     // 18 KB (lane stride 36)

    const int t = threadIdx.x;
    const int lane = t & 31;
    const int warp = t >> 5;
    const int brow = blockIdx.y * 128;
    const int bcol = blockIdx.x * 128;
    const int wm = (warp >> 1) * 32;
    const int wn = (warp & 1) * 64;
    const int qm = lane >> 2;
    const int qk = lane & 3;

    float acc[2][8][4];
#pragma unroll
    for (int mi = 0; mi < 2; ++mi)
#pragma unroll
        for (int ni = 0; ni < 8; ++ni)
#pragma unroll
            for (int q = 0; q < 4; ++q) acc[mi][ni][q] = 0.f;

    const int a_m0 = t >> 3;
    const int a_kg = t & 7;
    const int b_n0 = (t & 31) * 4;
    const int b_k0 = t >> 5;
    const int a_kt = a_kg >> 1;
    const int a_ik = a_kg & 1;

    for (int k0 = 0; k0 < K; k0 += 32) {
#pragma unroll
        for (int it = 0; it < 4; ++it) {
            int m = a_m0 + 32 * it;
            int grow = brow + m;
            int gk = k0 + a_kg * 4;
            float4 v = make_float4(0.f, 0.f, 0.f, 0.f);
            if (grow < M && gk < K)
                v = *reinterpret_cast<const float4*>(&A[(size_t)grow * K + gk]);
            int mt = m >> 4;
            int qmw = m & 7;
            int idx = ((m >> 3) & 1) + 2 * a_ik;
            uint32_t* dst = &Af[mt][a_kt][0];
            dst[(qmw * 4 + 0) * 4 + idx] = f2tf32(v.x);
            dst[(qmw * 4 + 1) * 4 + idx] = f2tf32(v.y);
            dst[(qmw * 4 + 2) * 4 + idx] = f2tf32(v.z);
            dst[(qmw * 4 + 3) * 4 + idx] = f2tf32(v.w);
        }
#pragma unroll
        for (int it = 0; it < 4; ++it) {
            int kr = b_k0 + 8 * it;
            int gk = k0 + kr;
            int gn = bcol + b_n0;
            float4 v = make_float4(0.f, 0.f, 0.f, 0.f);
            if (gk < K && gn < N)
                v = *reinterpret_cast<const float4*>(&B[(size_t)gk * N + gn]);
            int kt = kr >> 3;
            int qkb = kr & 3;
            int slot = (kr >> 2) & 1;
            uint32_t* dst = &Bf[kt][0];
            float vv[4] = {v.x, v.y, v.z, v.w};
#pragma unroll
            for (int j = 0; j < 4; ++j) {
                int nn = b_n0 + j;
                int nt = nn >> 3;
                int qmb = nn & 7;
                dst[(qmb * 4 + qkb) * 36 + nt * 2 + slot] = f2tf32(vv[j]);
            }
        }
        __syncthreads();

#pragma unroll
        for (int kk = 0; kk < 4; ++kk) {
            uint32_t af[2][4];
            *reinterpret_cast<uint4*>(af[0]) =
                *reinterpret_cast<const uint4*>(&Af[wm >> 4][kk][lane * 4]);
            *reinterpret_cast<uint4*>(af[1]) =
                *reinterpret_cast<const uint4*>(&Af[(wm >> 4) + 1][kk][lane * 4]);
            uint32_t bfv[8][2];
            const uint32_t* bp = &Bf[kk][lane * 36 + (wn >> 2)];
            *reinterpret_cast<uint4*>(&bfv[0][0]) = *reinterpret_cast<const uint4*>(bp);
            *reinterpret_cast<uint4*>(&bfv[2][0]) = *reinterpret_cast<const uint4*>(bp + 4);
            *reinterpret_cast<uint4*>(&bfv[4][0]) = *reinterpret_cast<const uint4*>(bp + 8);
            *reinterpret_cast<uint4*>(&bfv[6][0]) = *reinterpret_cast<const uint4*>(bp + 12);
#pragma unroll
            for (int mi = 0; mi < 2; ++mi)
#pragma unroll
                for (int ni = 0; ni < 8; ++ni) {
                    asm volatile(
                        "mma.sync.aligned.m16n8k8.row.col.f32.tf32.tf32.f32 "
                        "{%0,%1,%2,%3}, {%4,%5,%6,%7}, {%8,%9}, {%0,%1,%2,%3};"
                        : "+f"(acc[mi][ni][0]), "+f"(acc[mi][ni][1]),
                          "+f"(acc[mi][ni][2]), "+f"(acc[mi][ni][3])
                        : "r"(af[mi][0]), "r"(af[mi][1]), "r"(af[mi][2]), "r"(af[mi][3]),
                          "r"(bfv[ni][0]), "r"(bfv[ni][1]));
                }
        }
        __syncthreads();
    }

#pragma unroll
    for (int mi = 0; mi < 2; ++mi) {
#pragma unroll
        for (int ni = 0; ni < 8; ++ni) {
            int r0 = brow + wm + mi * 16 + qm;
            int cc = bcol + wn + ni * 8 + 2 * qk;
            if (cc + 1 < N) {
                if (r0 < M)
                    *reinterpret_cast<float2*>(&C[(size_t)r0 * N + cc]) =
                        make_float2(acc[mi][ni][0], acc[mi][ni][1]);
                if (r0 + 8 < M)
                    *reinterpret_cast<float2*>(&C[(size_t)(r0 + 8) * N + cc]) =
                        make_float2(acc[mi][ni][2], acc[mi][ni][3]);
            } else if (cc < N) {
                if (r0 < M) C[(size_t)r0 * N + cc] = acc[mi][ni][0];
                if (r0 + 8 < M) C[(size_t)(r0 + 8) * N + cc] = acc[mi][ni][2];
            }
        }
    }
}

// ---------------- GATv2 4-head edge kernel: half-warp pairs, peeled tail ---
__global__ void gat4_kernel(const float* __restrict__ xlr, int ld,
                            const float* __restrict__ att,
                            const float* __restrict__ bias,
                            const float* __restrict__ resid, int ldr,
                            const float* __restrict__ res_b,
                            const float* __restrict__ bn_g, const float* __restrict__ bn_b,
                            const float* __restrict__ bn_m, const float* __restrict__ bn_v,
                            float* __restrict__ out, int do_relu,
                            const int* __restrict__ offs, const int* __restrict__ csr,
                            int n) {
    int warp = (blockIdx.x * blockDim.x + threadIdx.x) >> 5;
    int lane = threadIdx.x & 31;
    if (warp >= n) return;
    const int i = warp;
    const int half = lane >> 4;
    const int ch = (lane & 15) * 8;

    const float* xrrow = xlr + (size_t)i * ld + 128 + ch;
    const float4 xr0 = *reinterpret_cast<const float4*>(xrrow);
    const float4 xr1 = *reinterpret_cast<const float4*>(xrrow + 4);
    const float4 at0 = *reinterpret_cast<const float4*>(att + ch);
    const float4 at1 = *reinterpret_cast<const float4*>(att + ch + 4);

    float dsum = 0.f;
    float4 acc0 = make_float4(0.f, 0.f, 0.f, 0.f);
    float4 acc1 = make_float4(0.f, 0.f, 0.f, 0.f);

    int e0 = offs[i];
    int deg = offs[i + 1] - e0;
    int tot = deg + 1;          // + implicit self-loop (index deg)
    int npair = (tot + 1) >> 1;

    int idx0 = half;
    int s0 = (idx0 < deg) ? csr[e0 + idx0] : i;
    const float* r0p = xlr + (size_t)s0 * ld + ch;
    float4 v0 = *reinterpret_cast<const float4*>(r0p);
    float4 v1 = *reinterpret_cast<const float4*>(r0p + 4);

    int k = 0;
    // main loop: pairs 0..npair-2, indices provably < tot (always valid)
    for (; k + 1 < npair; ++k) {
        float4 c0 = v0, c1 = v1;
        int idxn = 2 * (k + 1) + half;
        int sn = (idxn < deg) ? csr[e0 + idxn] : i;
        const float* rn = xlr + (size_t)sn * ld + ch;
        v0 = *reinterpret_cast<const float4*>(rn);
        v1 = *reinterpret_cast<const float4*>(rn + 4);
        float u, p;
        u = c0.x + xr0.x; u = fmaxf(u, 0.2f * u); p = u * at0.x;
        u = c0.y + xr0.y; u = fmaxf(u, 0.2f * u); p = fmaf(u, at0.y, p);
        u = c0.z + xr0.z; u = fmaxf(u, 0.2f * u); p = fmaf(u, at0.z, p);
        u = c0.w + xr0.w; u = fmaxf(u, 0.2f * u); p = fmaf(u, at0.w, p);
        u = c1.x + xr1.x; u = fmaxf(u, 0.2f * u); p = fmaf(u, at1.x, p);
        u = c1.y + xr1.y; u = fmaxf(u, 0.2f * u); p = fmaf(u, at1.y, p);
        u = c1.z + xr1.z; u = fmaxf(u, 0.2f * u); p = fmaf(u, at1.z, p);
        u = c1.w + xr1.w; u = fmaxf(u, 0.2f * u); p = fmaf(u, at1.w, p);
        p += __shfl_xor_sync(0xffffffffu, p, 1);
        p += __shfl_xor_sync(0xffffffffu, p, 2);
        float w = __expf(p);
        dsum += w;
        acc0.x = fmaf(w, c0.x, acc0.x);
        acc0.y = fmaf(w, c0.y, acc0.y);
        acc0.z = fmaf(w, c0.z, acc0.z);
        acc0.w = fmaf(w, c0.w, acc0.w);
        acc1.x = fmaf(w, c1.x, acc1.x);
        acc1.y = fmaf(w, c1.y, acc1.y);
        acc1.z = fmaf(w, c1.z, acc1.z);
        acc1.w = fmaf(w, c1.w, acc1.w);
    }
    // peeled final pair (half 1 may be past the end when tot is odd)
    {
        float4 c0 = v0, c1 = v1;
        bool valid = (2 * k + half) < tot;
        float u, p;
        u = c0.x + xr0.x; u = fmaxf(u, 0.2f * u); p = u * at0.x;
        u = c0.y + xr0.y; u = fmaxf(u, 0.2f * u); p = fmaf(u, at0.y, p);
        u = c0.z + xr0.z; u = fmaxf(u, 0.2f * u); p = fmaf(u, at0.z, p);
        u = c0.w + xr0.w; u = fmaxf(u, 0.2f * u); p = fmaf(u, at0.w, p);
        u = c1.x + xr1.x; u = fmaxf(u, 0.2f * u); p = fmaf(u, at1.x, p);
        u = c1.y + xr1.y; u = fmaxf(u, 0.2f * u); p = fmaf(u, at1.y, p);
        u = c1.z + xr1.z; u = fmaxf(u, 0.2f * u); p = fmaf(u, at1.z, p);
        u = c1.w + xr1.w; u = fmaxf(u, 0.2f * u); p = fmaf(u, at1.w, p);
        p += __shfl_xor_sync(0xffffffffu, p, 1);
        p += __shfl_xor_sync(0xffffffffu, p, 2);
        float w = valid ? __expf(p) : 0.f;
        dsum += w;
        acc0.x = fmaf(w, c0.x, acc0.x);
        acc0.y = fmaf(w, c0.y, acc0.y);
        acc0.z = fmaf(w, c0.z, acc0.z);
        acc0.w = fmaf(w, c0.w, acc0.w);
        acc1.x = fmaf(w, c1.x, acc1.x);
        acc1.y = fmaf(w, c1.y, acc1.y);
        acc1.z = fmaf(w, c1.z, acc1.z);
        acc1.w = fmaf(w, c1.w, acc1.w);
    }

    // merge the two halves
    dsum += __shfl_xor_sync(0xffffffffu, dsum, 16);
    acc0.x += __shfl_xor_sync(0xffffffffu, acc0.x, 16);
    acc0.y += __shfl_xor_sync(0xffffffffu, acc0.y, 16);
    acc0.z += __shfl_xor_sync(0xffffffffu, acc0.z, 16);
    acc0.w += __shfl_xor_sync(0xffffffffu, acc0.w, 16);
    acc1.x += __shfl_xor_sync(0xffffffffu, acc1.x, 16);
    acc1.y += __shfl_xor_sync(0xffffffffu, acc1.y, 16);
    acc1.z += __shfl_xor_sync(0xffffffffu, acc1.z, 16);
    acc1.w += __shfl_xor_sync(0xffffffffu, acc1.w, 16);

    if (half == 0) {
        float inv = 1.f / dsum;
        float4 bi0 = *reinterpret_cast<const float4*>(bias + ch);
        float4 bi1 = *reinterpret_cast<const float4*>(bias + ch + 4);
        const float* rr = resid + (size_t)i * ldr + ch;
        float4 rs0 = *reinterpret_cast<const float4*>(rr);
        float4 rs1 = *reinterpret_cast<const float4*>(rr + 4);
        float4 o0, o1;
        o0.x = acc0.x * inv + bi0.x + rs0.x;
        o0.y = acc0.y * inv + bi0.y + rs0.y;
        o0.z = acc0.z * inv + bi0.z + rs0.z;
        o0.w = acc0.w * inv + bi0.w + rs0.w;
        o1.x = acc1.x * inv + bi1.x + rs1.x;
        o1.y = acc1.y * inv + bi1.y + rs1.y;
        o1.z = acc1.z * inv + bi1.z + rs1.z;
        o1.w = acc1.w * inv + bi1.w + rs1.w;
        if (res_b) {
            float4 rb0 = *reinterpret_cast<const float4*>(res_b + ch);
            float4 rb1 = *reinterpret_cast<const float4*>(res_b + ch + 4);
            o0.x += rb0.x; o0.y += rb0.y; o0.z += rb0.z; o0.w += rb0.w;
            o1.x += rb1.x; o1.y += rb1.y; o1.z += rb1.z; o1.w += rb1.w;
        }
        float4 g0 = *reinterpret_cast<const float4*>(bn_g + ch);
        float4 g1 = *reinterpret_cast<const float4*>(bn_g + ch + 4);
        float4 bb0 = *reinterpret_cast<const float4*>(bn_b + ch);
        float4 bb1 = *reinterpret_cast<const float4*>(bn_b + ch + 4);
        float4 mm0 = *reinterpret_cast<const float4*>(bn_m + ch);
        float4 mm1 = *reinterpret_cast<const float4*>(bn_m + ch + 4);
        float4 vv0 = *reinterpret_cast<const float4*>(bn_v + ch);
        float4 vv1 = *reinterpret_cast<const float4*>(bn_v + ch + 4);
        o0.x = (o0.x - mm0.x) * rsqrtf(vv0.x + 1e-5f) * g0.x + bb0.x;
        o0.y = (o0.y - mm0.y) * rsqrtf(vv0.y + 1e-5f) * g0.y + bb0.y;
        o0.z = (o0.z - mm0.z) * rsqrtf(vv0.z + 1e-5f) * g0.z + bb0.z;
        o0.w = (o0.w - mm0.w) * rsqrtf(vv0.w + 1e-5f) * g0.w + bb0.w;
        o1.x = (o1.x - mm1.x) * rsqrtf(vv1.x + 1e-5f) * g1.x + bb1.x;
        o1.y = (o1.y - mm1.y) * rsqrtf(vv1.y + 1e-5f) * g1.y + bb1.y;
        o1.z = (o1.z - mm1.z) * rsqrtf(vv1.z + 1e-5f) * g1.z + bb1.z;
        o1.w = (o1.w - mm1.w) * rsqrtf(vv1.w + 1e-5f) * g1.w + bb1.w;
        if (do_relu) {
            o0.x = fmaxf(o0.x, 0.f); o0.y = fmaxf(o0.y, 0.f);
            o0.z = fmaxf(o0.z, 0.f); o0.w = fmaxf(o0.w, 0.f);
            o1.x = fmaxf(o1.x, 0.f); o1.y = fmaxf(o1.y, 0.f);
            o1.z = fmaxf(o1.z, 0.f); o1.w = fmaxf(o1.w, 0.f);
        }
        float* orow = out + (size_t)i * 128 + ch;
        *reinterpret_cast<float4*>(orow) = o0;
        *reinterpret_cast<float4*>(orow + 4) = o1;
    }
}

// ---------------- layer-3 GAT (heads=1, ch=47): half-warp pairs ------------
// xl slot is 64 wide with TRUE ZEROS in cols 47..63 and attp zero beyond 47,
// so lanes j>=12 contribute exactly 0 to logits and accumulators -> no
// predication needed in the hot loop. xr garbage (j>=12) is killed by att=0.
__global__ void gat1_kernel(const float* __restrict__ xlr,
                            const float* __restrict__ attp,
                            const float* __restrict__ bias,
                            const float* __restrict__ res_b,
                            const float* __restrict__ bn_g, const float* __restrict__ bn_b,
                            const float* __restrict__ bn_m, const float* __restrict__ bn_v,
                            float* __restrict__ out,
                            const int* __restrict__ offs, const int* __restrict__ csr,
                            int n) {
    int warp = (blockIdx.x * blockDim.x + threadIdx.x) >> 5;
    int lane = threadIdx.x & 31;
    if (warp >= n) return;
    const int i = warp;
    const int ld = 160;
    const int half = lane >> 4;
    const int j4 = (lane & 15) * 4;   // channel offset 0..60 within padded 64

    const float4 xrv = *reinterpret_cast<const float4*>(xlr + (size_t)i * ld + 64 + j4);
    const float4 attv = *reinterpret_cast<const float4*>(attp + j4);

    float dsum = 0.f;
    float4 acc = make_float4(0.f, 0.f, 0.f, 0.f);

    int e0 = offs[i];
    int deg = offs[i + 1] - e0;
    int tot = deg + 1;
    int npair = (tot + 1) >> 1;

    int s0 = (half < deg) ? csr[e0 + half] : i;
    float4 v = *reinterpret_cast<const float4*>(xlr + (size_t)s0 * ld + j4);

    int k = 0;
    for (; k + 1 < npair; ++k) {
        float4 cur = v;
        int idxn = 2 * (k + 1) + half;
        int sn = (idxn < deg) ? csr[e0 + idxn] : i;
        v = *reinterpret_cast<const float4*>(xlr + (size_t)sn * ld + j4);
        float u, p;
        u = cur.x + xrv.x; u = fmaxf(u, 0.2f * u); p = u * attv.x;
        u = cur.y + xrv.y; u = fmaxf(u, 0.2f * u); p = fmaf(u, attv.y, p);
        u = cur.z + xrv.z; u = fmaxf(u, 0.2f * u); p = fmaf(u, attv.z, p);
        u = cur.w + xrv.w; u = fmaxf(u, 0.2f * u); p = fmaf(u, attv.w, p);
        p += __shfl_xor_sync(0xffffffffu, p, 1);
        p += __shfl_xor_sync(0xffffffffu, p, 2);
        p += __shfl_xor_sync(0xffffffffu, p, 4);
        p += __shfl_xor_sync(0xffffffffu, p, 8);
        float w = __expf(p);
        dsum += w;
        acc.x = fmaf(w, cur.x, acc.x);
        acc.y = fmaf(w, cur.y, acc.y);
        acc.z = fmaf(w, cur.z, acc.z);
        acc.w = fmaf(w, cur.w, acc.w);
    }
    {
        float4 cur = v;
        bool valid = (2 * k + half) < tot;
        float u, p;
        u = cur.x + xrv.x; u = fmaxf(u, 0.2f * u); p = u * attv.x;
        u = cur.y + xrv.y; u = fmaxf(u, 0.2f * u); p = fmaf(u, attv.y, p);
        u = cur.z + xrv.z; u = fmaxf(u, 0.2f * u); p = fmaf(u, attv.z, p);
        u = cur.w + xrv.w; u = fmaxf(u, 0.2f * u); p = fmaf(u, attv.w, p);
        p += __shfl_xor_sync(0xffffffffu, p, 1);
        p += __shfl_xor_sync(0xffffffffu, p, 2);
        p += __shfl_xor_sync(0xffffffffu, p, 4);
        p += __shfl_xor_sync(0xffffffffu, p, 8);
        float w = valid ? __expf(p) : 0.f;
        dsum += w;
        acc.x = fmaf(w, cur.x, acc.x);
        acc.y = fmaf(w, cur.y, acc.y);
        acc.z = fmaf(w, cur.z, acc.z);
        acc.w = fmaf(w, cur.w, acc.w);
    }

    // merge halves
    dsum += __shfl_xor_sync(0xffffffffu, dsum, 16);
    acc.x += __shfl_xor_sync(0xffffffffu, acc.x, 16);
    acc.y += __shfl_xor_sync(0xffffffffu, acc.y, 16);
    acc.z += __shfl_xor_sync(0xffffffffu, acc.z, 16);
    acc.w += __shfl_xor_sync(0xffffffffu, acc.w, 16);

    if (half == 0 && j4 < 48) {
        float inv = 1.f / dsum;
        const float* resrow = xlr + (size_t)i * ld + 112;
        float a4[4] = {acc.x, acc.y, acc.z, acc.w};
#pragma unroll
        for (int q = 0; q < 4; ++q) {
            int c = j4 + q;
            if (c < 47) {
                float v2 = a4[q] * inv + bias[c] + resrow[c] + res_b[c];
                v2 = (v2 - bn_m[c]) * rsqrtf(bn_v[c] + 1e-5f) * bn_g[c] + bn_b[c];
                out[(size_t)i * 47 + c] = v2;
            }
        }
    }
}

// ---------------- host launch ---------------------------------------------
extern "C" void kernel_launch(void* const* d_in, const int* in_sizes, int n_in,
                              void* d_out, int out_size) {
    const float* x = (const float*)d_in[0];
    const int* ei = (const int*)d_in[1];
    const float* w1_src = (const float*)d_in[2];
    const float* w1_dst = (const float*)d_in[3];
    const float* att1 = (const float*)d_in[4];
    const float* b1 = (const float*)d_in[5];
    const float* bn1_g = (const float*)d_in[6];
    const float* bn1_b = (const float*)d_in[7];
    const float* bn1_m = (const float*)d_in[8];
    const float* bn1_v = (const float*)d_in[9];
    const float* res0_w = (const float*)d_in[10];
    const float* res0_b = (const float*)d_in[11];
    const float* w2_src = (const float*)d_in[12];
    const float* w2_dst = (const float*)d_in[13];
    const float* att2 = (const float*)d_in[14];
    const float* b2 = (const float*)d_in[15];
    const float* bn2_g = (const float*)d_in[16];
    const float* bn2_b = (const float*)d_in[17];
    const float* bn2_m = (const float*)d_in[18];
    const float* bn2_v = (const float*)d_in[19];
    const float* w3_src = (const float*)d_in[20];
    const float* w3_dst = (const float*)d_in[21];
    const float* att3 = (const float*)d_in[22];
    const float* b3 = (const float*)d_in[23];
    const float* bn3_g = (const float*)d_in[24];
    const float* bn3_b = (const float*)d_in[25];
    const float* bn3_m = (const float*)d_in[26];
    const float* bn3_v = (const float*)d_in[27];
    const float* res2_w = (const float*)d_in[28];
    const float* res2_b = (const float*)d_in[29];

    int n = in_sizes[0] / 100;
    int e = in_sizes[1] / 2;
    if (n > NN) n = NN;
    if (e > EE) e = EE;
    const int* srcp = ei;
    const int* dstp = ei + e;

    float *g1, *h1, *g2, *h2, *g3, *w1b, *w2b, *w3b, *att3p;
    int *cnt, *offs, *cur, *csr, *bsum, *boff;
    cudaGetSymbolAddress((void**)&g1, g_g1);
    cudaGetSymbolAddress((void**)&h1, g_h1);
    cudaGetSymbolAddress((void**)&g2, g_g2);
    cudaGetSymbolAddress((void**)&h2, g_h2);
    cudaGetSymbolAddress((void**)&g3, g_g3);
    cudaGetSymbolAddress((void**)&w1b, g_w1);
    cudaGetSymbolAddress((void**)&w2b, g_w2);
    cudaGetSymbolAddress((void**)&w3b, g_w3);
    cudaGetSymbolAddress((void**)&att3p, g_att3p);
    cudaGetSymbolAddress((void**)&cnt, g_cnt);
    cudaGetSymbolAddress((void**)&offs, g_offs);
    cudaGetSymbolAddress((void**)&cur, g_cur);
    cudaGetSymbolAddress((void**)&csr, g_csr);
    cudaGetSymbolAddress((void**)&bsum, g_bsum);
    cudaGetSymbolAddress((void**)&boff, g_boff);

    int gatBlocks = (n + 7) / 8;
    int rowsB = (n + 127) / 128;
    int edgeBlocks = (e + 1023) / 1024;  // 4 edges per thread
    int scanBlocks = (n + 255) / 256;    // 196 for n=50000

    prep_kernel<<<148, 256>>>(w1_src, w1_dst, res0_w, w2_src, w2_dst,
                              w3_src, w3_dst, res2_w, att3,
                              w1b, w2b, w3b, att3p, cnt, n);
    hist_kernel<<<edgeBlocks, 256>>>(dstp, cnt, e);
    scanA_kernel<<<scanBlocks, 256>>>(cnt, bsum, n);
    scanB_kernel<<<1, 256>>>(bsum, boff, scanBlocks);
    scanC_kernel<<<scanBlocks, 256>>>(cnt, boff, offs, cur, n);
    scatter_kernel<<<edgeBlocks, 256>>>(srcp, dstp, cur, csr, e);
    sgemm_tf32_kernel<<<dim3(3, rowsB), 256>>>(x, w1b, g1, n, 384, 100);

    // ----- layer 1 -----
    gat4_kernel<<<gatBlocks, 256>>>(g1, 384, att1, b1,
                                    g1 + 256, 384, res0_b,
                                    bn1_g, bn1_b, bn1_m, bn1_v,
                                    h1, 1, offs, csr, n);

    // ----- layer 2 -----
    sgemm_tf32_kernel<<<dim3(2, rowsB), 256>>>(h1, w2b, g2, n, 256, 128);
    gat4_kernel<<<gatBlocks, 256>>>(g2, 256, att2, b2,
                                    h1, 128, nullptr,
                                    bn2_g, bn2_b, bn2_m, bn2_v,
                                    h2, 1, offs, csr, n);

    // ----- layer 3 -----
    sgemm_tf32_kernel<<<dim3(2, rowsB), 256>>>(h2, w3b, g3, n, 160, 128);
    gat1_kernel<<<gatBlocks, 256>>>(g3, att3p, b3, res2_b,
                                    bn3_g, bn3_b, bn3_m, bn3_v,
                                    (float*)d_out, offs, csr, n);
}

// round 14
// speedup vs baseline: 1.1423x; 1.0016x over previous
#include <cuda_runtime.h>
#include <math.h>
#include <stdint.h>

// Problem constants (fixed by the dataset)
#define NN 50000
#define EE 800000

// ---------------- scratch (static device globals; no allocation) ----------
__device__ float g_g1[(size_t)NN * 384];  // [xl1 | xr1 | res1]
__device__ float g_h1[(size_t)NN * 128];
__device__ float g_g2[(size_t)NN * 256];  // [xl2 | xr2]
__device__ float g_h2[(size_t)NN * 128];
__device__ float g_g3[(size_t)NN * 160];  // [xl3:64 | xr3:48 | res3:48]
__device__ float g_w1[100 * 384];
__device__ float g_w2[128 * 256];
__device__ float g_w3[128 * 160];
__device__ float g_att3p[128];
__device__ int g_cnt[NN];
__device__ int g_offs[NN + 1];
__device__ int g_cur[NN];
__device__ int g_csr[EE];
__device__ int g_bsum[256];
__device__ int g_boff[256];

// ---------------- fused prep: zero cnt + pack w1/w2/w3 + pad att3 ----------
__global__ void prep_kernel(const float* __restrict__ w1_src, const float* __restrict__ w1_dst,
                            const float* __restrict__ res0_w,
                            const float* __restrict__ w2_src, const float* __restrict__ w2_dst,
                            const float* __restrict__ w3_src, const float* __restrict__ w3_dst,
                            const float* __restrict__ res2_w,
                            const float* __restrict__ att3,
                            float* __restrict__ w1b, float* __restrict__ w2b,
                            float* __restrict__ w3b, float* __restrict__ att3p,
                            int* __restrict__ cnt, int n) {
    const int W1T = 100 * 384;
    const int W2T = 128 * 256;
    const int W3T = 128 * 160;
    int total = n + W1T + W2T + W3T + 128;
    for (int idx = blockIdx.x * blockDim.x + threadIdx.x; idx < total;
         idx += gridDim.x * blockDim.x) {
        int r = idx;
        if (r < n) { cnt[r] = 0; continue; }
        r -= n;
        if (r < W1T) {
            int k = r / 384, col = r - k * 384;
            float v;
            if (col < 128) v = w1_src[k * 128 + col];
            else if (col < 256) v = w1_dst[k * 128 + col - 128];
            else v = res0_w[k * 128 + col - 256];
            w1b[r] = v;
            continue;
        }
        r -= W1T;
        if (r < W2T) {
            int k = r >> 8, col = r & 255;
            w2b[r] = (col < 128) ? w2_src[k * 128 + col] : w2_dst[k * 128 + col - 128];
            continue;
        }
        r -= W2T;
        if (r < W3T) {
            int k = r / 160, col = r - k * 160;
            float v = 0.f;
            if (col < 64) { if (col < 47) v = w3_src[k * 47 + col]; }
            else if (col < 112) { int c = col - 64; if (c < 47) v = w3_dst[k * 47 + c]; }
            else { int c = col - 112; if (c < 47) v = res2_w[k * 47 + c]; }
            w3b[r] = v;
            continue;
        }
        r -= W3T;
        att3p[r] = (r < 47) ? att3[r] : 0.f;
    }
}

// ---------------- CSR construction (4 edges/thread for MLP) ----------------
__global__ void hist_kernel(const int* __restrict__ dst, int* __restrict__ cnt, int e) {
    int base = (blockIdx.x * blockDim.x + threadIdx.x) * 4;
#pragma unroll
    for (int q = 0; q < 4; ++q) {
        int i = base + q;
        if (i < e) atomicAdd(&cnt[dst[i]], 1);
    }
}

__global__ void scanA_kernel(const int* __restrict__ cnt, int* __restrict__ bsum, int n) {
    __shared__ int sh[256];
    int t = threadIdx.x;
    int i = blockIdx.x * 256 + t;
    sh[t] = (i < n) ? cnt[i] : 0;
    __syncthreads();
    for (int off = 128; off > 0; off >>= 1) {
        if (t < off) sh[t] += sh[t + off];
        __syncthreads();
    }
    if (t == 0) bsum[blockIdx.x] = sh[0];
}

__global__ void scanB_kernel(const int* __restrict__ bsum, int* __restrict__ boff, int nb) {
    __shared__ int sh[256];
    int t = threadIdx.x;
    int v = (t < nb) ? bsum[t] : 0;
    sh[t] = v;
    __syncthreads();
    for (int off = 1; off < 256; off <<= 1) {
        int u = (t >= off) ? sh[t - off] : 0;
        __syncthreads();
        sh[t] += u;
        __syncthreads();
    }
    if (t < nb) boff[t] = sh[t] - v;  // exclusive
}

__global__ void scanC_kernel(const int* __restrict__ cnt, const int* __restrict__ boff,
                             int* __restrict__ offs, int* __restrict__ cur, int n) {
    __shared__ int sh[256];
    int t = threadIdx.x;
    int i = blockIdx.x * 256 + t;
    int v = (i < n) ? cnt[i] : 0;
    sh[t] = v;
    __syncthreads();
    for (int off = 1; off < 256; off <<= 1) {
        int u = (t >= off) ? sh[t - off] : 0;
        __syncthreads();
        sh[t] += u;
        __syncthreads();
    }
    int o = boff[blockIdx.x] + sh[t] - v;  // exclusive prefix
    if (i <= n) offs[i] = o;               // i == n -> total (pad cnt = 0)
    if (i < n) cur[i] = o;
}

__global__ void scatter_kernel(const int* __restrict__ src, const int* __restrict__ dst,
                               int* __restrict__ cur, int* __restrict__ csr, int e) {
    int base = (blockIdx.x * blockDim.x + threadIdx.x) * 4;
#pragma unroll
    for (int q = 0; q < 4; ++q) {
        int i = base + q;
        if (i < e) {
            int p = atomicAdd(&cur[dst[i]], 1);
            csr[p] = src[i];
        }
    }
}

// ---------------- TF32 tensor-core GEMM with fragment-order smem ----------
__device__ __forceinline__ uint32_t f2tf32(float f) {
    uint32_t u;
    asm("cvt.rna.tf32.f32 %0, %1;" : "=r"(u) : "f"(f));
    return u;
}

__global__ void __launch_bounds__(256, 2)
sgemm_tf32_kernel(const float* __restrict__ A, const float* __restrict__ B,
                  float* __restrict__ C, int M, int N, int K) {
    __shared__ uint32_t Af[8][4][128];   // 16 KB
    __shared__ uint32_t Bf[4][1152];     // 18 KB (lane stride 36)

    const int t = threadIdx.x;
    const int lane = t & 31;
    const int warp = t >> 5;
    const int brow = blockIdx.y * 128;
    const int bcol = blockIdx.x * 128;
    const int wm = (warp >> 1) * 32;
    const int wn = (warp & 1) * 64;
    const int qm = lane >> 2;
    const int qk = lane & 3;

    float acc[2][8][4];
#pragma unroll
    for (int mi = 0; mi < 2; ++mi)
#pragma unroll
        for (int ni = 0; ni < 8; ++ni)
#pragma unroll
            for (int q = 0; q < 4; ++q) acc[mi][ni][q] = 0.f;

    const int a_m0 = t >> 3;
    const int a_kg = t & 7;
    const int b_n0 = (t & 31) * 4;
    const int b_k0 = t >> 5;
    const int a_kt = a_kg >> 1;
    const int a_ik = a_kg & 1;

    for (int k0 = 0; k0 < K; k0 += 32) {
#pragma unroll
        for (int it = 0; it < 4; ++it) {
            int m = a_m0 + 32 * it;
            int grow = brow + m;
            int gk = k0 + a_kg * 4;
            float4 v = make_float4(0.f, 0.f, 0.f, 0.f);
            if (grow < M && gk < K)
                v = *reinterpret_cast<const float4*>(&A[(size_t)grow * K + gk]);
            int mt = m >> 4;
            int qmw = m & 7;
            int idx = ((m >> 3) & 1) + 2 * a_ik;
            uint32_t* dst = &Af[mt][a_kt][0];
            dst[(qmw * 4 + 0) * 4 + idx] = f2tf32(v.x);
            dst[(qmw * 4 + 1) * 4 + idx] = f2tf32(v.y);
            dst[(qmw * 4 + 2) * 4 + idx] = f2tf32(v.z);
            dst[(qmw * 4 + 3) * 4 + idx] = f2tf32(v.w);
        }
#pragma unroll
        for (int it = 0; it < 4; ++it) {
            int kr = b_k0 + 8 * it;
            int gk = k0 + kr;
            int gn = bcol + b_n0;
            float4 v = make_float4(0.f, 0.f, 0.f, 0.f);
            if (gk < K && gn < N)
                v = *reinterpret_cast<const float4*>(&B[(size_t)gk * N + gn]);
            int kt = kr >> 3;
            int qkb = kr & 3;
            int slot = (kr >> 2) & 1;
            uint32_t* dst = &Bf[kt][0];
            float vv[4] = {v.x, v.y, v.z, v.w};
#pragma unroll
            for (int j = 0; j < 4; ++j) {
                int nn = b_n0 + j;
                int nt = nn >> 3;
                int qmb = nn & 7;
                dst[(qmb * 4 + qkb) * 36 + nt * 2 + slot] = f2tf32(vv[j]);
            }
        }
        __syncthreads();

#pragma unroll
        for (int kk = 0; kk < 4; ++kk) {
            uint32_t af[2][4];
            *reinterpret_cast<uint4*>(af[0]) =
                *reinterpret_cast<const uint4*>(&Af[wm >> 4][kk][lane * 4]);
            *reinterpret_cast<uint4*>(af[1]) =
                *reinterpret_cast<const uint4*>(&Af[(wm >> 4) + 1][kk][lane * 4]);
            uint32_t bfv[8][2];
            const uint32_t* bp = &Bf[kk][lane * 36 + (wn >> 2)];
            *reinterpret_cast<uint4*>(&bfv[0][0]) = *reinterpret_cast<const uint4*>(bp);
            *reinterpret_cast<uint4*>(&bfv[2][0]) = *reinterpret_cast<const uint4*>(bp + 4);
            *reinterpret_cast<uint4*>(&bfv[4][0]) = *reinterpret_cast<const uint4*>(bp + 8);
            *reinterpret_cast<uint4*>(&bfv[6][0]) = *reinterpret_cast<const uint4*>(bp + 12);
#pragma unroll
            for (int mi = 0; mi < 2; ++mi)
#pragma unroll
                for (int ni = 0; ni < 8; ++ni) {
                    asm volatile(
                        "mma.sync.aligned.m16n8k8.row.col.f32.tf32.tf32.f32 "
                        "{%0,%1,%2,%3}, {%4,%5,%6,%7}, {%8,%9}, {%0,%1,%2,%3};"
                        : "+f"(acc[mi][ni][0]), "+f"(acc[mi][ni][1]),
                          "+f"(acc[mi][ni][2]), "+f"(acc[mi][ni][3])
                        : "r"(af[mi][0]), "r"(af[mi][1]), "r"(af[mi][2]), "r"(af[mi][3]),
                          "r"(bfv[ni][0]), "r"(bfv[ni][1]));
                }
        }
        __syncthreads();
    }

#pragma unroll
    for (int mi = 0; mi < 2; ++mi) {
#pragma unroll
        for (int ni = 0; ni < 8; ++ni) {
            int r0 = brow + wm + mi * 16 + qm;
            int cc = bcol + wn + ni * 8 + 2 * qk;
            if (cc + 1 < N) {
                if (r0 < M)
                    *reinterpret_cast<float2*>(&C[(size_t)r0 * N + cc]) =
                        make_float2(acc[mi][ni][0], acc[mi][ni][1]);
                if (r0 + 8 < M)
                    *reinterpret_cast<float2*>(&C[(size_t)(r0 + 8) * N + cc]) =
                        make_float2(acc[mi][ni][2], acc[mi][ni][3]);
            } else if (cc < N) {
                if (r0 < M) C[(size_t)r0 * N + cc] = acc[mi][ni][0];
                if (r0 + 8 < M) C[(size_t)(r0 + 8) * N + cc] = acc[mi][ni][2];
            }
        }
    }
}

// ---------------- GATv2 4-head edge kernel: half-warp pairs, peeled tail ---
__global__ void gat4_kernel(const float* __restrict__ xlr, int ld,
                            const float* __restrict__ att,
                            const float* __restrict__ bias,
                            const float* __restrict__ resid, int ldr,
                            const float* __restrict__ res_b,
                            const float* __restrict__ bn_g, const float* __restrict__ bn_b,
                            const float* __restrict__ bn_m, const float* __restrict__ bn_v,
                            float* __restrict__ out, int do_relu,
                            const int* __restrict__ offs, const int* __restrict__ csr,
                            int n) {
    int warp = (blockIdx.x * blockDim.x + threadIdx.x) >> 5;
    int lane = threadIdx.x & 31;
    if (warp >= n) return;
    const int i = warp;
    const int half = lane >> 4;
    const int ch = (lane & 15) * 8;

    const float* xrrow = xlr + (size_t)i * ld + 128 + ch;
    const float4 xr0 = *reinterpret_cast<const float4*>(xrrow);
    const float4 xr1 = *reinterpret_cast<const float4*>(xrrow + 4);
    const float4 at0 = *reinterpret_cast<const float4*>(att + ch);
    const float4 at1 = *reinterpret_cast<const float4*>(att + ch + 4);

    float dsum = 0.f;
    float4 acc0 = make_float4(0.f, 0.f, 0.f, 0.f);
    float4 acc1 = make_float4(0.f, 0.f, 0.f, 0.f);

    int e0 = offs[i];
    int deg = offs[i + 1] - e0;
    int tot = deg + 1;          // + implicit self-loop (index deg)
    int npair = (tot + 1) >> 1;

    int idx0 = half;
    int s0 = (idx0 < deg) ? csr[e0 + idx0] : i;
    const float* r0p = xlr + (size_t)s0 * ld + ch;
    float4 v0 = *reinterpret_cast<const float4*>(r0p);
    float4 v1 = *reinterpret_cast<const float4*>(r0p + 4);

    int k = 0;
    // main loop: pairs 0..npair-2, indices provably < tot (always valid)
    for (; k + 1 < npair; ++k) {
        float4 c0 = v0, c1 = v1;
        int idxn = 2 * (k + 1) + half;
        int sn = (idxn < deg) ? csr[e0 + idxn] : i;
        const float* rn = xlr + (size_t)sn * ld + ch;
        v0 = *reinterpret_cast<const float4*>(rn);
        v1 = *reinterpret_cast<const float4*>(rn + 4);
        float u, p;
        u = c0.x + xr0.x; u = fmaxf(u, 0.2f * u); p = u * at0.x;
        u = c0.y + xr0.y; u = fmaxf(u, 0.2f * u); p = fmaf(u, at0.y, p);
        u = c0.z + xr0.z; u = fmaxf(u, 0.2f * u); p = fmaf(u, at0.z, p);
        u = c0.w + xr0.w; u = fmaxf(u, 0.2f * u); p = fmaf(u, at0.w, p);
        u = c1.x + xr1.x; u = fmaxf(u, 0.2f * u); p = fmaf(u, at1.x, p);
        u = c1.y + xr1.y; u = fmaxf(u, 0.2f * u); p = fmaf(u, at1.y, p);
        u = c1.z + xr1.z; u = fmaxf(u, 0.2f * u); p = fmaf(u, at1.z, p);
        u = c1.w + xr1.w; u = fmaxf(u, 0.2f * u); p = fmaf(u, at1.w, p);
        p += __shfl_xor_sync(0xffffffffu, p, 1);
        p += __shfl_xor_sync(0xffffffffu, p, 2);
        float w = __expf(p);
        dsum += w;
        acc0.x = fmaf(w, c0.x, acc0.x);
        acc0.y = fmaf(w, c0.y, acc0.y);
        acc0.z = fmaf(w, c0.z, acc0.z);
        acc0.w = fmaf(w, c0.w, acc0.w);
        acc1.x = fmaf(w, c1.x, acc1.x);
        acc1.y = fmaf(w, c1.y, acc1.y);
        acc1.z = fmaf(w, c1.z, acc1.z);
        acc1.w = fmaf(w, c1.w, acc1.w);
    }
    // peeled final pair (half 1 may be past the end when tot is odd)
    {
        float4 c0 = v0, c1 = v1;
        bool valid = (2 * k + half) < tot;
        float u, p;
        u = c0.x + xr0.x; u = fmaxf(u, 0.2f * u); p = u * at0.x;
        u = c0.y + xr0.y; u = fmaxf(u, 0.2f * u); p = fmaf(u, at0.y, p);
        u = c0.z + xr0.z; u = fmaxf(u, 0.2f * u); p = fmaf(u, at0.z, p);
        u = c0.w + xr0.w; u = fmaxf(u, 0.2f * u); p = fmaf(u, at0.w, p);
        u = c1.x + xr1.x; u = fmaxf(u, 0.2f * u); p = fmaf(u, at1.x, p);
        u = c1.y + xr1.y; u = fmaxf(u, 0.2f * u); p = fmaf(u, at1.y, p);
        u = c1.z + xr1.z; u = fmaxf(u, 0.2f * u); p = fmaf(u, at1.z, p);
        u = c1.w + xr1.w; u = fmaxf(u, 0.2f * u); p = fmaf(u, at1.w, p);
        p += __shfl_xor_sync(0xffffffffu, p, 1);
        p += __shfl_xor_sync(0xffffffffu, p, 2);
        float w = valid ? __expf(p) : 0.f;
        dsum += w;
        acc0.x = fmaf(w, c0.x, acc0.x);
        acc0.y = fmaf(w, c0.y, acc0.y);
        acc0.z = fmaf(w, c0.z, acc0.z);
        acc0.w = fmaf(w, c0.w, acc0.w);
        acc1.x = fmaf(w, c1.x, acc1.x);
        acc1.y = fmaf(w, c1.y, acc1.y);
        acc1.z = fmaf(w, c1.z, acc1.z);
        acc1.w = fmaf(w, c1.w, acc1.w);
    }

    // merge the two halves
    dsum += __shfl_xor_sync(0xffffffffu, dsum, 16);
    acc0.x += __shfl_xor_sync(0xffffffffu, acc0.x, 16);
    acc0.y += __shfl_xor_sync(0xffffffffu, acc0.y, 16);
    acc0.z += __shfl_xor_sync(0xffffffffu, acc0.z, 16);
    acc0.w += __shfl_xor_sync(0xffffffffu, acc0.w, 16);
    acc1.x += __shfl_xor_sync(0xffffffffu, acc1.x, 16);
    acc1.y += __shfl_xor_sync(0xffffffffu, acc1.y, 16);
    acc1.z += __shfl_xor_sync(0xffffffffu, acc1.z, 16);
    acc1.w += __shfl_xor_sync(0xffffffffu, acc1.w, 16);

    if (half == 0) {
        float inv = 1.f / dsum;
        float4 bi0 = *reinterpret_cast<const float4*>(bias + ch);
        float4 bi1 = *reinterpret_cast<const float4*>(bias + ch + 4);
        const float* rr = resid + (size_t)i * ldr + ch;
        float4 rs0 = *reinterpret_cast<const float4*>(rr);
        float4 rs1 = *reinterpret_cast<const float4*>(rr + 4);
        float4 o0, o1;
        o0.x = acc0.x * inv + bi0.x + rs0.x;
        o0.y = acc0.y * inv + bi0.y + rs0.y;
        o0.z = acc0.z * inv + bi0.z + rs0.z;
        o0.w = acc0.w * inv + bi0.w + rs0.w;
        o1.x = acc1.x * inv + bi1.x + rs1.x;
        o1.y = acc1.y * inv + bi1.y + rs1.y;
        o1.z = acc1.z * inv + bi1.z + rs1.z;
        o1.w = acc1.w * inv + bi1.w + rs1.w;
        if (res_b) {
            float4 rb0 = *reinterpret_cast<const float4*>(res_b + ch);
            float4 rb1 = *reinterpret_cast<const float4*>(res_b + ch + 4);
            o0.x += rb0.x; o0.y += rb0.y; o0.z += rb0.z; o0.w += rb0.w;
            o1.x += rb1.x; o1.y += rb1.y; o1.z += rb1.z; o1.w += rb1.w;
        }
        float4 g0 = *reinterpret_cast<const float4*>(bn_g + ch);
        float4 g1 = *reinterpret_cast<const float4*>(bn_g + ch + 4);
        float4 bb0 = *reinterpret_cast<const float4*>(bn_b + ch);
        float4 bb1 = *reinterpret_cast<const float4*>(bn_b + ch + 4);
        float4 mm0 = *reinterpret_cast<const float4*>(bn_m + ch);
        float4 mm1 = *reinterpret_cast<const float4*>(bn_m + ch + 4);
        float4 vv0 = *reinterpret_cast<const float4*>(bn_v + ch);
        float4 vv1 = *reinterpret_cast<const float4*>(bn_v + ch + 4);
        o0.x = (o0.x - mm0.x) * rsqrtf(vv0.x + 1e-5f) * g0.x + bb0.x;
        o0.y = (o0.y - mm0.y) * rsqrtf(vv0.y + 1e-5f) * g0.y + bb0.y;
        o0.z = (o0.z - mm0.z) * rsqrtf(vv0.z + 1e-5f) * g0.z + bb0.z;
        o0.w = (o0.w - mm0.w) * rsqrtf(vv0.w + 1e-5f) * g0.w + bb0.w;
        o1.x = (o1.x - mm1.x) * rsqrtf(vv1.x + 1e-5f) * g1.x + bb1.x;
        o1.y = (o1.y - mm1.y) * rsqrtf(vv1.y + 1e-5f) * g1.y + bb1.y;
        o1.z = (o1.z - mm1.z) * rsqrtf(vv1.z + 1e-5f) * g1.z + bb1.z;
        o1.w = (o1.w - mm1.w) * rsqrtf(vv1.w + 1e-5f) * g1.w + bb1.w;
        if (do_relu) {
            o0.x = fmaxf(o0.x, 0.f); o0.y = fmaxf(o0.y, 0.f);
            o0.z = fmaxf(o0.z, 0.f); o0.w = fmaxf(o0.w, 0.f);
            o1.x = fmaxf(o1.x, 0.f); o1.y = fmaxf(o1.y, 0.f);
            o1.z = fmaxf(o1.z, 0.f); o1.w = fmaxf(o1.w, 0.f);
        }
        float* orow = out + (size_t)i * 128 + ch;
        *reinterpret_cast<float4*>(orow) = o0;
        *reinterpret_cast<float4*>(orow + 4) = o1;
    }
}

// ---------------- layer-3 GAT (heads=1, ch=47): half-warp pairs ------------
// xl slot is 64 wide with TRUE ZEROS in cols 47..63 and attp zero beyond 47,
// so lanes j>=12 contribute exactly 0 to logits and accumulators -> no
// predication needed in the hot loop. xr garbage (j>=12) is killed by att=0.
__global__ void gat1_kernel(const float* __restrict__ xlr,
                            const float* __restrict__ attp,
                            const float* __restrict__ bias,
                            const float* __restrict__ res_b,
                            const float* __restrict__ bn_g, const float* __restrict__ bn_b,
                            const float* __restrict__ bn_m, const float* __restrict__ bn_v,
                            float* __restrict__ out,
                            const int* __restrict__ offs, const int* __restrict__ csr,
                            int n) {
    int warp = (blockIdx.x * blockDim.x + threadIdx.x) >> 5;
    int lane = threadIdx.x & 31;
    if (warp >= n) return;
    const int i = warp;
    const int ld = 160;
    const int half = lane >> 4;
    const int j4 = (lane & 15) * 4;   // channel offset 0..60 within padded 64

    const float4 xrv = *reinterpret_cast<const float4*>(xlr + (size_t)i * ld + 64 + j4);
    const float4 attv = *reinterpret_cast<const float4*>(attp + j4);

    float dsum = 0.f;
    float4 acc = make_float4(0.f, 0.f, 0.f, 0.f);

    int e0 = offs[i];
    int deg = offs[i + 1] - e0;
    int tot = deg + 1;
    int npair = (tot + 1) >> 1;

    int s0 = (half < deg) ? csr[e0 + half] : i;
    float4 v = *reinterpret_cast<const float4*>(xlr + (size_t)s0 * ld + j4);

    int k = 0;
    for (; k + 1 < npair; ++k) {
        float4 cur = v;
        int idxn = 2 * (k + 1) + half;
        int sn = (idxn < deg) ? csr[e0 + idxn] : i;
        v = *reinterpret_cast<const float4*>(xlr + (size_t)sn * ld + j4);
        float u, p;
        u = cur.x + xrv.x; u = fmaxf(u, 0.2f * u); p = u * attv.x;
        u = cur.y + xrv.y; u = fmaxf(u, 0.2f * u); p = fmaf(u, attv.y, p);
        u = cur.z + xrv.z; u = fmaxf(u, 0.2f * u); p = fmaf(u, attv.z, p);
        u = cur.w + xrv.w; u = fmaxf(u, 0.2f * u); p = fmaf(u, attv.w, p);
        p += __shfl_xor_sync(0xffffffffu, p, 1);
        p += __shfl_xor_sync(0xffffffffu, p, 2);
        p += __shfl_xor_sync(0xffffffffu, p, 4);
        p += __shfl_xor_sync(0xffffffffu, p, 8);
        float w = __expf(p);
        dsum += w;
        acc.x = fmaf(w, cur.x, acc.x);
        acc.y = fmaf(w, cur.y, acc.y);
        acc.z = fmaf(w, cur.z, acc.z);
        acc.w = fmaf(w, cur.w, acc.w);
    }
    {
        float4 cur = v;
        bool valid = (2 * k + half) < tot;
        float u, p;
        u = cur.x + xrv.x; u = fmaxf(u, 0.2f * u); p = u * attv.x;
        u = cur.y + xrv.y; u = fmaxf(u, 0.2f * u); p = fmaf(u, attv.y, p);
        u = cur.z + xrv.z; u = fmaxf(u, 0.2f * u); p = fmaf(u, attv.z, p);
        u = cur.w + xrv.w; u = fmaxf(u, 0.2f * u); p = fmaf(u, attv.w, p);
        p += __shfl_xor_sync(0xffffffffu, p, 1);
        p += __shfl_xor_sync(0xffffffffu, p, 2);
        p += __shfl_xor_sync(0xffffffffu, p, 4);
        p += __shfl_xor_sync(0xffffffffu, p, 8);
        float w = valid ? __expf(p) : 0.f;
        dsum += w;
        acc.x = fmaf(w, cur.x, acc.x);
        acc.y = fmaf(w, cur.y, acc.y);
        acc.z = fmaf(w, cur.z, acc.z);
        acc.w = fmaf(w, cur.w, acc.w);
    }

    // merge halves
    dsum += __shfl_xor_sync(0xffffffffu, dsum, 16);
    acc.x += __shfl_xor_sync(0xffffffffu, acc.x, 16);
    acc.y += __shfl_xor_sync(0xffffffffu, acc.y, 16);
    acc.z += __shfl_xor_sync(0xffffffffu, acc.z, 16);
    acc.w += __shfl_xor_sync(0xffffffffu, acc.w, 16);

    if (half == 0 && j4 < 48) {
        float inv = 1.f / dsum;
        const float* resrow = xlr + (size_t)i * ld + 112;
        float a4[4] = {acc.x, acc.y, acc.z, acc.w};
#pragma unroll
        for (int q = 0; q < 4; ++q) {
            int c = j4 + q;
            if (c < 47) {
                float v2 = a4[q] * inv + bias[c] + resrow[c] + res_b[c];
                v2 = (v2 - bn_m[c]) * rsqrtf(bn_v[c] + 1e-5f) * bn_g[c] + bn_b[c];
                out[(size_t)i * 47 + c] = v2;
            }
        }
    }
}

// ---------------- host launch ---------------------------------------------
extern "C" void kernel_launch(void* const* d_in, const int* in_sizes, int n_in,
                              void* d_out, int out_size) {
    const float* x = (const float*)d_in[0];
    const int* ei = (const int*)d_in[1];
    const float* w1_src = (const float*)d_in[2];
    const float* w1_dst = (const float*)d_in[3];
    const float* att1 = (const float*)d_in[4];
    const float* b1 = (const float*)d_in[5];
    const float* bn1_g = (const float*)d_in[6];
    const float* bn1_b = (const float*)d_in[7];
    const float* bn1_m = (const float*)d_in[8];
    const float* bn1_v = (const float*)d_in[9];
    const float* res0_w = (const float*)d_in[10];
    const float* res0_b = (const float*)d_in[11];
    const float* w2_src = (const float*)d_in[12];
    const float* w2_dst = (const float*)d_in[13];
    const float* att2 = (const float*)d_in[14];
    const float* b2 = (const float*)d_in[15];
    const float* bn2_g = (const float*)d_in[16];
    const float* bn2_b = (const float*)d_in[17];
    const float* bn2_m = (const float*)d_in[18];
    const float* bn2_v = (const float*)d_in[19];
    const float* w3_src = (const float*)d_in[20];
    const float* w3_dst = (const float*)d_in[21];
    const float* att3 = (const float*)d_in[22];
    const float* b3 = (const float*)d_in[23];
    const float* bn3_g = (const float*)d_in[24];
    const float* bn3_b = (const float*)d_in[25];
    const float* bn3_m = (const float*)d_in[26];
    const float* bn3_v = (const float*)d_in[27];
    const float* res2_w = (const float*)d_in[28];
    const float* res2_b = (const float*)d_in[29];

    int n = in_sizes[0] / 100;
    int e = in_sizes[1] / 2;
    if (n > NN) n = NN;
    if (e > EE) e = EE;
    const int* srcp = ei;
    const int* dstp = ei + e;

    float *g1, *h1, *g2, *h2, *g3, *w1b, *w2b, *w3b, *att3p;
    int *cnt, *offs, *cur, *csr, *bsum, *boff;
    cudaGetSymbolAddress((void**)&g1, g_g1);
    cudaGetSymbolAddress((void**)&h1, g_h1);
    cudaGetSymbolAddress((void**)&g2, g_g2);
    cudaGetSymbolAddress((void**)&h2, g_h2);
    cudaGetSymbolAddress((void**)&g3, g_g3);
    cudaGetSymbolAddress((void**)&w1b, g_w1);
    cudaGetSymbolAddress((void**)&w2b, g_w2);
    cudaGetSymbolAddress((void**)&w3b, g_w3);
    cudaGetSymbolAddress((void**)&att3p, g_att3p);
    cudaGetSymbolAddress((void**)&cnt, g_cnt);
    cudaGetSymbolAddress((void**)&offs, g_offs);
    cudaGetSymbolAddress((void**)&cur, g_cur);
    cudaGetSymbolAddress((void**)&csr, g_csr);
    cudaGetSymbolAddress((void**)&bsum, g_bsum);
    cudaGetSymbolAddress((void**)&boff, g_boff);

    int gatBlocks = (n + 7) / 8;
    int rowsB = (n + 127) / 128;
    int edgeBlocks = (e + 1023) / 1024;  // 4 edges per thread
    int scanBlocks = (n + 255) / 256;    // 196 for n=50000

    prep_kernel<<<148, 256>>>(w1_src, w1_dst, res0_w, w2_src, w2_dst,
                              w3_src, w3_dst, res2_w, att3,
                              w1b, w2b, w3b, att3p, cnt, n);
    hist_kernel<<<edgeBlocks, 256>>>(dstp, cnt, e);
    scanA_kernel<<<scanBlocks, 256>>>(cnt, bsum, n);
    scanB_kernel<<<1, 256>>>(bsum, boff, scanBlocks);
    scanC_kernel<<<scanBlocks, 256>>>(cnt, boff, offs, cur, n);
    scatter_kernel<<<edgeBlocks, 256>>>(srcp, dstp, cur, csr, e);
    sgemm_tf32_kernel<<<dim3(3, rowsB), 256>>>(x, w1b, g1, n, 384, 100);

    // ----- layer 1 -----
    gat4_kernel<<<gatBlocks, 256>>>(g1, 384, att1, b1,
                                    g1 + 256, 384, res0_b,
                                    bn1_g, bn1_b, bn1_m, bn1_v,
                                    h1, 1, offs, csr, n);

    // ----- layer 2 -----
    sgemm_tf32_kernel<<<dim3(2, rowsB), 256>>>(h1, w2b, g2, n, 256, 128);
    gat4_kernel<<<gatBlocks, 256>>>(g2, 256, att2, b2,
                                    h1, 128, nullptr,
                                    bn2_g, bn2_b, bn2_m, bn2_v,
                                    h2, 1, offs, csr, n);

    // ----- layer 3 -----
    sgemm_tf32_kernel<<<dim3(2, rowsB), 256>>>(h2, w3b, g3, n, 160, 128);
    gat1_kernel<<<gatBlocks, 256>>>(g3, att3p, b3, res2_b,
                                    bn3_g, bn3_b, bn3_m, bn3_v,
                                    (float*)d_out, offs, csr, n);
}

// round 15
// speedup vs baseline: 1.1891x; 1.0409x over previous
#include <cuda_runtime.h>
#include <math.h>
#include <stdint.h>

// Problem constants (fixed by the dataset)
#define NN 50000
#define EE 800000

// ---------------- scratch (static device globals; no allocation) ----------
__device__ float g_g1[(size_t)NN * 384];  // [xl1 | xr1 | res1]
__device__ float g_h1[(size_t)NN * 128];
__device__ float g_g2[(size_t)NN * 256];  // [xl2 | xr2]
__device__ float g_h2[(size_t)NN * 128];
__device__ float g_g3[(size_t)NN * 160];  // [xl3:64 | xr3:48 | res3:48]
__device__ float g_w1[100 * 384];
__device__ float g_w2[128 * 256];
__device__ float g_w3[128 * 160];
__device__ float g_att3p[128];
__device__ int g_cnt[NN];
__device__ int g_offs[NN + 1];
__device__ int g_cur[NN];
__device__ int g_csr[EE];
__device__ int g_bsum[256];
__device__ int g_boff[256];

// ---------------- fused prep: zero cnt + pack w1/w2/w3 + pad att3 ----------
__global__ void prep_kernel(const float* __restrict__ w1_src, const float* __restrict__ w1_dst,
                            const float* __restrict__ res0_w,
                            const float* __restrict__ w2_src, const float* __restrict__ w2_dst,
                            const float* __restrict__ w3_src, const float* __restrict__ w3_dst,
                            const float* __restrict__ res2_w,
                            const float* __restrict__ att3,
                            float* __restrict__ w1b, float* __restrict__ w2b,
                            float* __restrict__ w3b, float* __restrict__ att3p,
                            int* __restrict__ cnt, int n) {
    const int W1T = 100 * 384;
    const int W2T = 128 * 256;
    const int W3T = 128 * 160;
    int total = n + W1T + W2T + W3T + 128;
    for (int idx = blockIdx.x * blockDim.x + threadIdx.x; idx < total;
         idx += gridDim.x * blockDim.x) {
        int r = idx;
        if (r < n) { cnt[r] = 0; continue; }
        r -= n;
        if (r < W1T) {
            int k = r / 384, col = r - k * 384;
            float v;
            if (col < 128) v = w1_src[k * 128 + col];
            else if (col < 256) v = w1_dst[k * 128 + col - 128];
            else v = res0_w[k * 128 + col - 256];
            w1b[r] = v;
            continue;
        }
        r -= W1T;
        if (r < W2T) {
            int k = r >> 8, col = r & 255;
            w2b[r] = (col < 128) ? w2_src[k * 128 + col] : w2_dst[k * 128 + col - 128];
            continue;
        }
        r -= W2T;
        if (r < W3T) {
            int k = r / 160, col = r - k * 160;
            float v = 0.f;
            if (col < 64) { if (col < 47) v = w3_src[k * 47 + col]; }
            else if (col < 112) { int c = col - 64; if (c < 47) v = w3_dst[k * 47 + c]; }
            else { int c = col - 112; if (c < 47) v = res2_w[k * 47 + c]; }
            w3b[r] = v;
            continue;
        }
        r -= W3T;
        att3p[r] = (r < 47) ? att3[r] : 0.f;
    }
}

// ---------------- CSR construction (4 edges/thread for MLP) ----------------
__global__ void hist_kernel(const int* __restrict__ dst, int* __restrict__ cnt, int e) {
    int base = (blockIdx.x * blockDim.x + threadIdx.x) * 4;
#pragma unroll
    for (int q = 0; q < 4; ++q) {
        int i = base + q;
        if (i < e) atomicAdd(&cnt[dst[i]], 1);
    }
}

__global__ void scanA_kernel(const int* __restrict__ cnt, int* __restrict__ bsum, int n) {
    __shared__ int sh[256];
    int t = threadIdx.x;
    int i = blockIdx.x * 256 + t;
    sh[t] = (i < n) ? cnt[i] : 0;
    __syncthreads();
    for (int off = 128; off > 0; off >>= 1) {
        if (t < off) sh[t] += sh[t + off];
        __syncthreads();
    }
    if (t == 0) bsum[blockIdx.x] = sh[0];
}

__global__ void scanB_kernel(const int* __restrict__ bsum, int* __restrict__ boff, int nb) {
    __shared__ int sh[256];
    int t = threadIdx.x;
    int v = (t < nb) ? bsum[t] : 0;
    sh[t] = v;
    __syncthreads();
    for (int off = 1; off < 256; off <<= 1) {
        int u = (t >= off) ? sh[t - off] : 0;
        __syncthreads();
        sh[t] += u;
        __syncthreads();
    }
    if (t < nb) boff[t] = sh[t] - v;  // exclusive
}

__global__ void scanC_kernel(const int* __restrict__ cnt, const int* __restrict__ boff,
                             int* __restrict__ offs, int* __restrict__ cur, int n) {
    __shared__ int sh[256];
    int t = threadIdx.x;
    int i = blockIdx.x * 256 + t;
    int v = (i < n) ? cnt[i] : 0;
    sh[t] = v;
    __syncthreads();
    for (int off = 1; off < 256; off <<= 1) {
        int u = (t >= off) ? sh[t - off] : 0;
        __syncthreads();
        sh[t] += u;
        __syncthreads();
    }
    int o = boff[blockIdx.x] + sh[t] - v;  // exclusive prefix
    if (i <= n) offs[i] = o;               // i == n -> total (pad cnt = 0)
    if (i < n) cur[i] = o;
}

__global__ void scatter_kernel(const int* __restrict__ src, const int* __restrict__ dst,
                               int* __restrict__ cur, int* __restrict__ csr, int e) {
    int base = (blockIdx.x * blockDim.x + threadIdx.x) * 4;
#pragma unroll
    for (int q = 0; q < 4; ++q) {
        int i = base + q;
        if (i < e) {
            int p = atomicAdd(&cur[dst[i]], 1);
            csr[p] = src[i];
        }
    }
}

// ---------------- TF32 GEMM: B fully smem-resident, A double-buffered ------
// Dynamic smem: Bf[4 tiles][4 kk][1152] + Af[2 bufs][8 mt][4 kt][128]
//   = 18432 + 8192 u32 = 106496 bytes. 2 CTAs/SM (208 KB <= 228 KB).
// A-fragment store swizzled by (kt*8) XOR to cut fill bank conflicts;
// read side compensates with the compile-time kk constant.
__device__ __forceinline__ uint32_t f2tf32(float f) {
    uint32_t u;
    asm("cvt.rna.tf32.f32 %0, %1;" : "=r"(u) : "f"(f));
    return u;
}

__global__ void __launch_bounds__(256, 2)
sgemm_tf32_kernel(const float* __restrict__ A, const float* __restrict__ B,
                  float* __restrict__ C, int M, int N, int K) {
    extern __shared__ uint32_t smemraw[];
    uint32_t* Bf = smemraw;            // (t*4 + kk) * 1152
    uint32_t* Afb = smemraw + 18432;   // buf*4096 + mt*512 + kt*128

    const int t = threadIdx.x;
    const int lane = t & 31;
    const int warp = t >> 5;
    const int brow = blockIdx.y * 128;
    const int bcol = blockIdx.x * 128;
    const int wm = (warp >> 1) * 32;
    const int wn = (warp & 1) * 64;
    const int qm = lane >> 2;
    const int qk = lane & 3;

    const int a_m0 = t >> 3;
    const int a_kg = t & 7;
    const int b_n0 = (t & 31) * 4;
    const int b_k0 = t >> 5;
    const int a_kt = a_kg >> 1;
    const int a_ik = a_kg & 1;
    const int NT = (K + 31) >> 5;      // 4 for K=100/128

    float acc[2][8][4];
#pragma unroll
    for (int mi = 0; mi < 2; ++mi)
#pragma unroll
        for (int ni = 0; ni < 8; ++ni)
#pragma unroll
            for (int q = 0; q < 4; ++q) acc[mi][ni][q] = 0.f;

    // ---- prologue: load ALL B tiles into smem (stays for whole kernel) ----
    for (int tt = 0; tt < NT; ++tt) {
#pragma unroll
        for (int it = 0; it < 4; ++it) {
            int kr = b_k0 + 8 * it;
            int gk = tt * 32 + kr;
            int gn = bcol + b_n0;
            float4 v = make_float4(0.f, 0.f, 0.f, 0.f);
            if (gk < K && gn < N)
                v = *reinterpret_cast<const float4*>(&B[(size_t)gk * N + gn]);
            uint32_t* dstp = Bf + (tt * 4 + it) * 1152;
            int qkb = b_k0 & 3;
            int slot = (b_k0 >> 2) & 1;
            float vv[4] = {v.x, v.y, v.z, v.w};
#pragma unroll
            for (int j = 0; j < 4; ++j) {
                int nn = b_n0 + j;
                int nt = nn >> 3;
                int qmb = nn & 7;
                dstp[(qmb * 4 + qkb) * 36 + nt * 2 + slot] = f2tf32(vv[j]);
            }
        }
    }

    // ---- A tile 0: global -> regs -> smem buf 0 ----
    float4 apre[4];
#pragma unroll
    for (int it = 0; it < 4; ++it) {
        int grow = brow + a_m0 + 32 * it;
        int gk = a_kg * 4;
        apre[it] = make_float4(0.f, 0.f, 0.f, 0.f);
        if (grow < M && gk < K)
            apre[it] = *reinterpret_cast<const float4*>(&A[(size_t)grow * K + gk]);
    }
    {
        uint32_t* ab = Afb + a_kt * 128;
        const int sw = a_kt * 8;
#pragma unroll
        for (int it = 0; it < 4; ++it) {
            int m = a_m0 + 32 * it;
            int mt = m >> 4;
            int qmw = m & 7;
            int idx = ((m >> 3) & 1) + 2 * a_ik;
            uint32_t* d = ab + mt * 512;
            d[(((qmw * 4 + 0) * 4 + idx)) ^ sw] = f2tf32(apre[it].x);
            d[(((qmw * 4 + 1) * 4 + idx)) ^ sw] = f2tf32(apre[it].y);
            d[(((qmw * 4 + 2) * 4 + idx)) ^ sw] = f2tf32(apre[it].z);
            d[(((qmw * 4 + 3) * 4 + idx)) ^ sw] = f2tf32(apre[it].w);
        }
    }
    __syncthreads();

    // ---- main loop: 1 sync per tile; A LDG for t+1 overlaps compute of t --
    for (int tt = 0; tt < NT; ++tt) {
        if (tt + 1 < NT) {
#pragma unroll
            for (int it = 0; it < 4; ++it) {
                int grow = brow + a_m0 + 32 * it;
                int gk = (tt + 1) * 32 + a_kg * 4;
                apre[it] = make_float4(0.f, 0.f, 0.f, 0.f);
                if (grow < M && gk < K)
                    apre[it] = *reinterpret_cast<const float4*>(&A[(size_t)grow * K + gk]);
            }
        }

        const uint32_t* Ab = Afb + (tt & 1) * 4096;
#pragma unroll
        for (int kk = 0; kk < 4; ++kk) {
            const uint32_t* abase = Ab + kk * 128 + ((lane * 4) ^ (kk * 8));
            uint32_t af[2][4];
            *reinterpret_cast<uint4*>(af[0]) =
                *reinterpret_cast<const uint4*>(abase + (wm >> 4) * 512);
            *reinterpret_cast<uint4*>(af[1]) =
                *reinterpret_cast<const uint4*>(abase + ((wm >> 4) + 1) * 512);
            uint32_t bfv[8][2];
            const uint32_t* bp = Bf + (tt * 4 + kk) * 1152 + lane * 36 + (wn >> 2);
            *reinterpret_cast<uint4*>(&bfv[0][0]) = *reinterpret_cast<const uint4*>(bp);
            *reinterpret_cast<uint4*>(&bfv[2][0]) = *reinterpret_cast<const uint4*>(bp + 4);
            *reinterpret_cast<uint4*>(&bfv[4][0]) = *reinterpret_cast<const uint4*>(bp + 8);
            *reinterpret_cast<uint4*>(&bfv[6][0]) = *reinterpret_cast<const uint4*>(bp + 12);
#pragma unroll
            for (int mi = 0; mi < 2; ++mi)
#pragma unroll
                for (int ni = 0; ni < 8; ++ni) {
                    asm volatile(
                        "mma.sync.aligned.m16n8k8.row.col.f32.tf32.tf32.f32 "
                        "{%0,%1,%2,%3}, {%4,%5,%6,%7}, {%8,%9}, {%0,%1,%2,%3};"
                        : "+f"(acc[mi][ni][0]), "+f"(acc[mi][ni][1]),
                          "+f"(acc[mi][ni][2]), "+f"(acc[mi][ni][3])
                        : "r"(af[mi][0]), "r"(af[mi][1]), "r"(af[mi][2]), "r"(af[mi][3]),
                          "r"(bfv[ni][0]), "r"(bfv[ni][1]));
                }
        }

        if (tt + 1 < NT) {
            uint32_t* ab = Afb + ((tt + 1) & 1) * 4096 + a_kt * 128;
            const int sw = a_kt * 8;
#pragma unroll
            for (int it = 0; it < 4; ++it) {
                int m = a_m0 + 32 * it;
                int mt = m >> 4;
                int qmw = m & 7;
                int idx = ((m >> 3) & 1) + 2 * a_ik;
                uint32_t* d = ab + mt * 512;
                d[(((qmw * 4 + 0) * 4 + idx)) ^ sw] = f2tf32(apre[it].x);
                d[(((qmw * 4 + 1) * 4 + idx)) ^ sw] = f2tf32(apre[it].y);
                d[(((qmw * 4 + 2) * 4 + idx)) ^ sw] = f2tf32(apre[it].z);
                d[(((qmw * 4 + 3) * 4 + idx)) ^ sw] = f2tf32(apre[it].w);
            }
        }
        __syncthreads();
    }

#pragma unroll
    for (int mi = 0; mi < 2; ++mi) {
#pragma unroll
        for (int ni = 0; ni < 8; ++ni) {
            int r0 = brow + wm + mi * 16 + qm;
            int cc = bcol + wn + ni * 8 + 2 * qk;
            if (cc + 1 < N) {
                if (r0 < M)
                    *reinterpret_cast<float2*>(&C[(size_t)r0 * N + cc]) =
                        make_float2(acc[mi][ni][0], acc[mi][ni][1]);
                if (r0 + 8 < M)
                    *reinterpret_cast<float2*>(&C[(size_t)(r0 + 8) * N + cc]) =
                        make_float2(acc[mi][ni][2], acc[mi][ni][3]);
            } else if (cc < N) {
                if (r0 < M) C[(size_t)r0 * N + cc] = acc[mi][ni][0];
                if (r0 + 8 < M) C[(size_t)(r0 + 8) * N + cc] = acc[mi][ni][2];
            }
        }
    }
}

// ---------------- GATv2 4-head edge kernel: half-warp pairs, peeled tail ---
__global__ void gat4_kernel(const float* __restrict__ xlr, int ld,
                            const float* __restrict__ att,
                            const float* __restrict__ bias,
                            const float* __restrict__ resid, int ldr,
                            const float* __restrict__ res_b,
                            const float* __restrict__ bn_g, const float* __restrict__ bn_b,
                            const float* __restrict__ bn_m, const float* __restrict__ bn_v,
                            float* __restrict__ out, int do_relu,
                            const int* __restrict__ offs, const int* __restrict__ csr,
                            int n) {
    int warp = (blockIdx.x * blockDim.x + threadIdx.x) >> 5;
    int lane = threadIdx.x & 31;
    if (warp >= n) return;
    const int i = warp;
    const int half = lane >> 4;
    const int ch = (lane & 15) * 8;

    const float* xrrow = xlr + (size_t)i * ld + 128 + ch;
    const float4 xr0 = *reinterpret_cast<const float4*>(xrrow);
    const float4 xr1 = *reinterpret_cast<const float4*>(xrrow + 4);
    const float4 at0 = *reinterpret_cast<const float4*>(att + ch);
    const float4 at1 = *reinterpret_cast<const float4*>(att + ch + 4);

    float dsum = 0.f;
    float4 acc0 = make_float4(0.f, 0.f, 0.f, 0.f);
    float4 acc1 = make_float4(0.f, 0.f, 0.f, 0.f);

    int e0 = offs[i];
    int deg = offs[i + 1] - e0;
    int tot = deg + 1;          // + implicit self-loop (index deg)
    int npair = (tot + 1) >> 1;

    int idx0 = half;
    int s0 = (idx0 < deg) ? csr[e0 + idx0] : i;
    const float* r0p = xlr + (size_t)s0 * ld + ch;
    float4 v0 = *reinterpret_cast<const float4*>(r0p);
    float4 v1 = *reinterpret_cast<const float4*>(r0p + 4);

    int k = 0;
    for (; k + 1 < npair; ++k) {
        float4 c0 = v0, c1 = v1;
        int idxn = 2 * (k + 1) + half;
        int sn = (idxn < deg) ? csr[e0 + idxn] : i;
        const float* rn = xlr + (size_t)sn * ld + ch;
        v0 = *reinterpret_cast<const float4*>(rn);
        v1 = *reinterpret_cast<const float4*>(rn + 4);
        float u, p;
        u = c0.x + xr0.x; u = fmaxf(u, 0.2f * u); p = u * at0.x;
        u = c0.y + xr0.y; u = fmaxf(u, 0.2f * u); p = fmaf(u, at0.y, p);
        u = c0.z + xr0.z; u = fmaxf(u, 0.2f * u); p = fmaf(u, at0.z, p);
        u = c0.w + xr0.w; u = fmaxf(u, 0.2f * u); p = fmaf(u, at0.w, p);
        u = c1.x + xr1.x; u = fmaxf(u, 0.2f * u); p = fmaf(u, at1.x, p);
        u = c1.y + xr1.y; u = fmaxf(u, 0.2f * u); p = fmaf(u, at1.y, p);
        u = c1.z + xr1.z; u = fmaxf(u, 0.2f * u); p = fmaf(u, at1.z, p);
        u = c1.w + xr1.w; u = fmaxf(u, 0.2f * u); p = fmaf(u, at1.w, p);
        p += __shfl_xor_sync(0xffffffffu, p, 1);
        p += __shfl_xor_sync(0xffffffffu, p, 2);
        float w = __expf(p);
        dsum += w;
        acc0.x = fmaf(w, c0.x, acc0.x);
        acc0.y = fmaf(w, c0.y, acc0.y);
        acc0.z = fmaf(w, c0.z, acc0.z);
        acc0.w = fmaf(w, c0.w, acc0.w);
        acc1.x = fmaf(w, c1.x, acc1.x);
        acc1.y = fmaf(w, c1.y, acc1.y);
        acc1.z = fmaf(w, c1.z, acc1.z);
        acc1.w = fmaf(w, c1.w, acc1.w);
    }
    {
        float4 c0 = v0, c1 = v1;
        bool valid = (2 * k + half) < tot;
        float u, p;
        u = c0.x + xr0.x; u = fmaxf(u, 0.2f * u); p = u * at0.x;
        u = c0.y + xr0.y; u = fmaxf(u, 0.2f * u); p = fmaf(u, at0.y, p);
        u = c0.z + xr0.z; u = fmaxf(u, 0.2f * u); p = fmaf(u, at0.z, p);
        u = c0.w + xr0.w; u = fmaxf(u, 0.2f * u); p = fmaf(u, at0.w, p);
        u = c1.x + xr1.x; u = fmaxf(u, 0.2f * u); p = fmaf(u, at1.x, p);
        u = c1.y + xr1.y; u = fmaxf(u, 0.2f * u); p = fmaf(u, at1.y, p);
        u = c1.z + xr1.z; u = fmaxf(u, 0.2f * u); p = fmaf(u, at1.z, p);
        u = c1.w + xr1.w; u = fmaxf(u, 0.2f * u); p = fmaf(u, at1.w, p);
        p += __shfl_xor_sync(0xffffffffu, p, 1);
        p += __shfl_xor_sync(0xffffffffu, p, 2);
        float w = valid ? __expf(p) : 0.f;
        dsum += w;
        acc0.x = fmaf(w, c0.x, acc0.x);
        acc0.y = fmaf(w, c0.y, acc0.y);
        acc0.z = fmaf(w, c0.z, acc0.z);
        acc0.w = fmaf(w, c0.w, acc0.w);
        acc1.x = fmaf(w, c1.x, acc1.x);
        acc1.y = fmaf(w, c1.y, acc1.y);
        acc1.z = fmaf(w, c1.z, acc1.z);
        acc1.w = fmaf(w, c1.w, acc1.w);
    }

    dsum += __shfl_xor_sync(0xffffffffu, dsum, 16);
    acc0.x += __shfl_xor_sync(0xffffffffu, acc0.x, 16);
    acc0.y += __shfl_xor_sync(0xffffffffu, acc0.y, 16);
    acc0.z += __shfl_xor_sync(0xffffffffu, acc0.z, 16);
    acc0.w += __shfl_xor_sync(0xffffffffu, acc0.w, 16);
    acc1.x += __shfl_xor_sync(0xffffffffu, acc1.x, 16);
    acc1.y += __shfl_xor_sync(0xffffffffu, acc1.y, 16);
    acc1.z += __shfl_xor_sync(0xffffffffu, acc1.z, 16);
    acc1.w += __shfl_xor_sync(0xffffffffu, acc1.w, 16);

    if (half == 0) {
        float inv = 1.f / dsum;
        float4 bi0 = *reinterpret_cast<const float4*>(bias + ch);
        float4 bi1 = *reinterpret_cast<const float4*>(bias + ch + 4);
        const float* rr = resid + (size_t)i * ldr + ch;
        float4 rs0 = *reinterpret_cast<const float4*>(rr);
        float4 rs1 = *reinterpret_cast<const float4*>(rr + 4);
        float4 o0, o1;
        o0.x = acc0.x * inv + bi0.x + rs0.x;
        o0.y = acc0.y * inv + bi0.y + rs0.y;
        o0.z = acc0.z * inv + bi0.z + rs0.z;
        o0.w = acc0.w * inv + bi0.w + rs0.w;
        o1.x = acc1.x * inv + bi1.x + rs1.x;
        o1.y = acc1.y * inv + bi1.y + rs1.y;
        o1.z = acc1.z * inv + bi1.z + rs1.z;
        o1.w = acc1.w * inv + bi1.w + rs1.w;
        if (res_b) {
            float4 rb0 = *reinterpret_cast<const float4*>(res_b + ch);
            float4 rb1 = *reinterpret_cast<const float4*>(res_b + ch + 4);
            o0.x += rb0.x; o0.y += rb0.y; o0.z += rb0.z; o0.w += rb0.w;
            o1.x += rb1.x; o1.y += rb1.y; o1.z += rb1.z; o1.w += rb1.w;
        }
        float4 g0 = *reinterpret_cast<const float4*>(bn_g + ch);
        float4 g1 = *reinterpret_cast<const float4*>(bn_g + ch + 4);
        float4 bb0 = *reinterpret_cast<const float4*>(bn_b + ch);
        float4 bb1 = *reinterpret_cast<const float4*>(bn_b + ch + 4);
        float4 mm0 = *reinterpret_cast<const float4*>(bn_m + ch);
        float4 mm1 = *reinterpret_cast<const float4*>(bn_m + ch + 4);
        float4 vv0 = *reinterpret_cast<const float4*>(bn_v + ch);
        float4 vv1 = *reinterpret_cast<const float4*>(bn_v + ch + 4);
        o0.x = (o0.x - mm0.x) * rsqrtf(vv0.x + 1e-5f) * g0.x + bb0.x;
        o0.y = (o0.y - mm0.y) * rsqrtf(vv0.y + 1e-5f) * g0.y + bb0.y;
        o0.z = (o0.z - mm0.z) * rsqrtf(vv0.z + 1e-5f) * g0.z + bb0.z;
        o0.w = (o0.w - mm0.w) * rsqrtf(vv0.w + 1e-5f) * g0.w + bb0.w;
        o1.x = (o1.x - mm1.x) * rsqrtf(vv1.x + 1e-5f) * g1.x + bb1.x;
        o1.y = (o1.y - mm1.y) * rsqrtf(vv1.y + 1e-5f) * g1.y + bb1.y;
        o1.z = (o1.z - mm1.z) * rsqrtf(vv1.z + 1e-5f) * g1.z + bb1.z;
        o1.w = (o1.w - mm1.w) * rsqrtf(vv1.w + 1e-5f) * g1.w + bb1.w;
        if (do_relu) {
            o0.x = fmaxf(o0.x, 0.f); o0.y = fmaxf(o0.y, 0.f);
            o0.z = fmaxf(o0.z, 0.f); o0.w = fmaxf(o0.w, 0.f);
            o1.x = fmaxf(o1.x, 0.f); o1.y = fmaxf(o1.y, 0.f);
            o1.z = fmaxf(o1.z, 0.f); o1.w = fmaxf(o1.w, 0.f);
        }
        float* orow = out + (size_t)i * 128 + ch;
        *reinterpret_cast<float4*>(orow) = o0;
        *reinterpret_cast<float4*>(orow + 4) = o1;
    }
}

// ---------------- layer-3 GAT (heads=1, ch=47): half-warp pairs ------------
__global__ void gat1_kernel(const float* __restrict__ xlr,
                            const float* __restrict__ attp,
                            const float* __restrict__ bias,
                            const float* __restrict__ res_b,
                            const float* __restrict__ bn_g, const float* __restrict__ bn_b,
                            const float* __restrict__ bn_m, const float* __restrict__ bn_v,
                            float* __restrict__ out,
                            const int* __restrict__ offs, const int* __restrict__ csr,
                            int n) {
    int warp = (blockIdx.x * blockDim.x + threadIdx.x) >> 5;
    int lane = threadIdx.x & 31;
    if (warp >= n) return;
    const int i = warp;
    const int ld = 160;
    const int half = lane >> 4;
    const int j4 = (lane & 15) * 4;

    const float4 xrv = *reinterpret_cast<const float4*>(xlr + (size_t)i * ld + 64 + j4);
    const float4 attv = *reinterpret_cast<const float4*>(attp + j4);

    float dsum = 0.f;
    float4 acc = make_float4(0.f, 0.f, 0.f, 0.f);

    int e0 = offs[i];
    int deg = offs[i + 1] - e0;
    int tot = deg + 1;
    int npair = (tot + 1) >> 1;

    int s0 = (half < deg) ? csr[e0 + half] : i;
    float4 v = *reinterpret_cast<const float4*>(xlr + (size_t)s0 * ld + j4);

    int k = 0;
    for (; k + 1 < npair; ++k) {
        float4 cur = v;
        int idxn = 2 * (k + 1) + half;
        int sn = (idxn < deg) ? csr[e0 + idxn] : i;
        v = *reinterpret_cast<const float4*>(xlr + (size_t)sn * ld + j4);
        float u, p;
        u = cur.x + xrv.x; u = fmaxf(u, 0.2f * u); p = u * attv.x;
        u = cur.y + xrv.y; u = fmaxf(u, 0.2f * u); p = fmaf(u, attv.y, p);
        u = cur.z + xrv.z; u = fmaxf(u, 0.2f * u); p = fmaf(u, attv.z, p);
        u = cur.w + xrv.w; u = fmaxf(u, 0.2f * u); p = fmaf(u, attv.w, p);
        p += __shfl_xor_sync(0xffffffffu, p, 1);
        p += __shfl_xor_sync(0xffffffffu, p, 2);
        p += __shfl_xor_sync(0xffffffffu, p, 4);
        p += __shfl_xor_sync(0xffffffffu, p, 8);
        float w = __expf(p);
        dsum += w;
        acc.x = fmaf(w, cur.x, acc.x);
        acc.y = fmaf(w, cur.y, acc.y);
        acc.z = fmaf(w, cur.z, acc.z);
        acc.w = fmaf(w, cur.w, acc.w);
    }
    {
        float4 cur = v;
        bool valid = (2 * k + half) < tot;
        float u, p;
        u = cur.x + xrv.x; u = fmaxf(u, 0.2f * u); p = u * attv.x;
        u = cur.y + xrv.y; u = fmaxf(u, 0.2f * u); p = fmaf(u, attv.y, p);
        u = cur.z + xrv.z; u = fmaxf(u, 0.2f * u); p = fmaf(u, attv.z, p);
        u = cur.w + xrv.w; u = fmaxf(u, 0.2f * u); p = fmaf(u, attv.w, p);
        p += __shfl_xor_sync(0xffffffffu, p, 1);
        p += __shfl_xor_sync(0xffffffffu, p, 2);
        p += __shfl_xor_sync(0xffffffffu, p, 4);
        p += __shfl_xor_sync(0xffffffffu, p, 8);
        float w = valid ? __expf(p) : 0.f;
        dsum += w;
        acc.x = fmaf(w, cur.x, acc.x);
        acc.y = fmaf(w, cur.y, acc.y);
        acc.z = fmaf(w, cur.z, acc.z);
        acc.w = fmaf(w, cur.w, acc.w);
    }

    dsum += __shfl_xor_sync(0xffffffffu, dsum, 16);
    acc.x += __shfl_xor_sync(0xffffffffu, acc.x, 16);
    acc.y += __shfl_xor_sync(0xffffffffu, acc.y, 16);
    acc.z += __shfl_xor_sync(0xffffffffu, acc.z, 16);
    acc.w += __shfl_xor_sync(0xffffffffu, acc.w, 16);

    if (half == 0 && j4 < 48) {
        float inv = 1.f / dsum;
        const float* resrow = xlr + (size_t)i * ld + 112;
        float a4[4] = {acc.x, acc.y, acc.z, acc.w};
#pragma unroll
        for (int q = 0; q < 4; ++q) {
            int c = j4 + q;
            if (c < 47) {
                float v2 = a4[q] * inv + bias[c] + resrow[c] + res_b[c];
                v2 = (v2 - bn_m[c]) * rsqrtf(bn_v[c] + 1e-5f) * bn_g[c] + bn_b[c];
                out[(size_t)i * 47 + c] = v2;
            }
        }
    }
}

// ---------------- host launch ---------------------------------------------
extern "C" void kernel_launch(void* const* d_in, const int* in_sizes, int n_in,
                              void* d_out, int out_size) {
    const float* x = (const float*)d_in[0];
    const int* ei = (const int*)d_in[1];
    const float* w1_src = (const float*)d_in[2];
    const float* w1_dst = (const float*)d_in[3];
    const float* att1 = (const float*)d_in[4];
    const float* b1 = (const float*)d_in[5];
    const float* bn1_g = (const float*)d_in[6];
    const float* bn1_b = (const float*)d_in[7];
    const float* bn1_m = (const float*)d_in[8];
    const float* bn1_v = (const float*)d_in[9];
    const float* res0_w = (const float*)d_in[10];
    const float* res0_b = (const float*)d_in[11];
    const float* w2_src = (const float*)d_in[12];
    const float* w2_dst = (const float*)d_in[13];
    const float* att2 = (const float*)d_in[14];
    const float* b2 = (const float*)d_in[15];
    const float* bn2_g = (const float*)d_in[16];
    const float* bn2_b = (const float*)d_in[17];
    const float* bn2_m = (const float*)d_in[18];
    const float* bn2_v = (const float*)d_in[19];
    const float* w3_src = (const float*)d_in[20];
    const float* w3_dst = (const float*)d_in[21];
    const float* att3 = (const float*)d_in[22];
    const float* b3 = (const float*)d_in[23];
    const float* bn3_g = (const float*)d_in[24];
    const float* bn3_b = (const float*)d_in[25];
    const float* bn3_m = (const float*)d_in[26];
    const float* bn3_v = (const float*)d_in[27];
    const float* res2_w = (const float*)d_in[28];
    const float* res2_b = (const float*)d_in[29];

    int n = in_sizes[0] / 100;
    int e = in_sizes[1] / 2;
    if (n > NN) n = NN;
    if (e > EE) e = EE;
    const int* srcp = ei;
    const int* dstp = ei + e;

    float *g1, *h1, *g2, *h2, *g3, *w1b, *w2b, *w3b, *att3p;
    int *cnt, *offs, *cur, *csr, *bsum, *boff;
    cudaGetSymbolAddress((void**)&g1, g_g1);
    cudaGetSymbolAddress((void**)&h1, g_h1);
    cudaGetSymbolAddress((void**)&g2, g_g2);
    cudaGetSymbolAddress((void**)&h2, g_h2);
    cudaGetSymbolAddress((void**)&g3, g_g3);
    cudaGetSymbolAddress((void**)&w1b, g_w1);
    cudaGetSymbolAddress((void**)&w2b, g_w2);
    cudaGetSymbolAddress((void**)&w3b, g_w3);
    cudaGetSymbolAddress((void**)&att3p, g_att3p);
    cudaGetSymbolAddress((void**)&cnt, g_cnt);
    cudaGetSymbolAddress((void**)&offs, g_offs);
    cudaGetSymbolAddress((void**)&cur, g_cur);
    cudaGetSymbolAddress((void**)&csr, g_csr);
    cudaGetSymbolAddress((void**)&bsum, g_bsum);
    cudaGetSymbolAddress((void**)&boff, g_boff);

    int gatBlocks = (n + 7) / 8;
    int rowsB = (n + 127) / 128;
    int edgeBlocks = (e + 1023) / 1024;
    int scanBlocks = (n + 255) / 256;

    const int GEMM_SMEM = (4 * 4 * 1152 + 2 * 8 * 4 * 128) * 4;  // 106496 B
    cudaFuncSetAttribute(sgemm_tf32_kernel,
                         cudaFuncAttributeMaxDynamicSharedMemorySize, GEMM_SMEM);

    prep_kernel<<<148, 256>>>(w1_src, w1_dst, res0_w, w2_src, w2_dst,
                              w3_src, w3_dst, res2_w, att3,
                              w1b, w2b, w3b, att3p, cnt, n);
    hist_kernel<<<edgeBlocks, 256>>>(dstp, cnt, e);
    scanA_kernel<<<scanBlocks, 256>>>(cnt, bsum, n);
    scanB_kernel<<<1, 256>>>(bsum, boff, scanBlocks);
    scanC_kernel<<<scanBlocks, 256>>>(cnt, boff, offs, cur, n);
    scatter_kernel<<<edgeBlocks, 256>>>(srcp, dstp, cur, csr, e);
    sgemm_tf32_kernel<<<dim3(3, rowsB), 256, GEMM_SMEM>>>(x, w1b, g1, n, 384, 100);

    // ----- layer 1 -----
    gat4_kernel<<<gatBlocks, 256>>>(g1, 384, att1, b1,
                                    g1 + 256, 384, res0_b,
                                    bn1_g, bn1_b, bn1_m, bn1_v,
                                    h1, 1, offs, csr, n);

    // ----- layer 2 -----
    sgemm_tf32_kernel<<<dim3(2, rowsB), 256, GEMM_SMEM>>>(h1, w2b, g2, n, 256, 128);
    gat4_kernel<<<gatBlocks, 256>>>(g2, 256, att2, b2,
                                    h1, 128, nullptr,
                                    bn2_g, bn2_b, bn2_m, bn2_v,
                                    h2, 1, offs, csr, n);

    // ----- layer 3 -----
    sgemm_tf32_kernel<<<dim3(2, rowsB), 256, GEMM_SMEM>>>(h2, w3b, g3, n, 160, 128);
    gat1_kernel<<<gatBlocks, 256>>>(g3, att3p, b3, res2_b,
                                    bn3_g, bn3_b, bn3_m, bn3_v,
                                    (float*)d_out, offs, csr, n);
}

// round 16
// speedup vs baseline: 1.1896x; 1.0004x over previous
#include <cuda_runtime.h>
#include <math.h>
#include <stdint.h>

// Problem constants (fixed by the dataset)
#define NN 50000
#define EE 800000

// ---------------- scratch (static device globals; no allocation) ----------
__device__ float g_g1[(size_t)NN * 384];  // [xl1 | xr1 | res1]
__device__ float g_h1[(size_t)NN * 128];
__device__ float g_g2[(size_t)NN * 256];  // [xl2 | xr2]
__device__ float g_h2[(size_t)NN * 128];
__device__ float g_g3[(size_t)NN * 160];  // [xl3:64 | xr3:48 | res3:48]
__device__ float g_w1[100 * 384];
__device__ float g_w2[128 * 256];
__device__ float g_w3[128 * 160];
__device__ float g_att3p[128];
__device__ int g_cnt[NN];
__device__ int g_offs[NN + 1];
__device__ int g_cur[NN];
__device__ int g_csr[EE];
__device__ int g_bsum[256];
__device__ int g_boff[256];

// ---------------- fused prep: zero cnt + pack w1/w2/w3 + pad att3 ----------
__global__ void prep_kernel(const float* __restrict__ w1_src, const float* __restrict__ w1_dst,
                            const float* __restrict__ res0_w,
                            const float* __restrict__ w2_src, const float* __restrict__ w2_dst,
                            const float* __restrict__ w3_src, const float* __restrict__ w3_dst,
                            const float* __restrict__ res2_w,
                            const float* __restrict__ att3,
                            float* __restrict__ w1b, float* __restrict__ w2b,
                            float* __restrict__ w3b, float* __restrict__ att3p,
                            int* __restrict__ cnt, int n) {
    const int W1T = 100 * 384;
    const int W2T = 128 * 256;
    const int W3T = 128 * 160;
    int total = n + W1T + W2T + W3T + 128;
    for (int idx = blockIdx.x * blockDim.x + threadIdx.x; idx < total;
         idx += gridDim.x * blockDim.x) {
        int r = idx;
        if (r < n) { cnt[r] = 0; continue; }
        r -= n;
        if (r < W1T) {
            int k = r / 384, col = r - k * 384;
            float v;
            if (col < 128) v = w1_src[k * 128 + col];
            else if (col < 256) v = w1_dst[k * 128 + col - 128];
            else v = res0_w[k * 128 + col - 256];
            w1b[r] = v;
            continue;
        }
        r -= W1T;
        if (r < W2T) {
            int k = r >> 8, col = r & 255;
            w2b[r] = (col < 128) ? w2_src[k * 128 + col] : w2_dst[k * 128 + col - 128];
            continue;
        }
        r -= W2T;
        if (r < W3T) {
            int k = r / 160, col = r - k * 160;
            float v = 0.f;
            if (col < 64) { if (col < 47) v = w3_src[k * 47 + col]; }
            else if (col < 112) { int c = col - 64; if (c < 47) v = w3_dst[k * 47 + c]; }
            else { int c = col - 112; if (c < 47) v = res2_w[k * 47 + c]; }
            w3b[r] = v;
            continue;
        }
        r -= W3T;
        att3p[r] = (r < 47) ? att3[r] : 0.f;
    }
}

// ---------------- CSR construction (4 edges/thread for MLP) ----------------
__global__ void hist_kernel(const int* __restrict__ dst, int* __restrict__ cnt, int e) {
    int base = (blockIdx.x * blockDim.x + threadIdx.x) * 4;
#pragma unroll
    for (int q = 0; q < 4; ++q) {
        int i = base + q;
        if (i < e) atomicAdd(&cnt[dst[i]], 1);
    }
}

__global__ void scanA_kernel(const int* __restrict__ cnt, int* __restrict__ bsum, int n) {
    __shared__ int sh[256];
    int t = threadIdx.x;
    int i = blockIdx.x * 256 + t;
    sh[t] = (i < n) ? cnt[i] : 0;
    __syncthreads();
    for (int off = 128; off > 0; off >>= 1) {
        if (t < off) sh[t] += sh[t + off];
        __syncthreads();
    }
    if (t == 0) bsum[blockIdx.x] = sh[0];
}

__global__ void scanB_kernel(const int* __restrict__ bsum, int* __restrict__ boff, int nb) {
    __shared__ int sh[256];
    int t = threadIdx.x;
    int v = (t < nb) ? bsum[t] : 0;
    sh[t] = v;
    __syncthreads();
    for (int off = 1; off < 256; off <<= 1) {
        int u = (t >= off) ? sh[t - off] : 0;
        __syncthreads();
        sh[t] += u;
        __syncthreads();
    }
    if (t < nb) boff[t] = sh[t] - v;  // exclusive
}

__global__ void scanC_kernel(const int* __restrict__ cnt, const int* __restrict__ boff,
                             int* __restrict__ offs, int* __restrict__ cur, int n) {
    __shared__ int sh[256];
    int t = threadIdx.x;
    int i = blockIdx.x * 256 + t;
    int v = (i < n) ? cnt[i] : 0;
    sh[t] = v;
    __syncthreads();
    for (int off = 1; off < 256; off <<= 1) {
        int u = (t >= off) ? sh[t - off] : 0;
        __syncthreads();
        sh[t] += u;
        __syncthreads();
    }
    int o = boff[blockIdx.x] + sh[t] - v;  // exclusive prefix
    if (i <= n) offs[i] = o;               // i == n -> total (pad cnt = 0)
    if (i < n) cur[i] = o;
}

__global__ void scatter_kernel(const int* __restrict__ src, const int* __restrict__ dst,
                               int* __restrict__ cur, int* __restrict__ csr, int e) {
    int base = (blockIdx.x * blockDim.x + threadIdx.x) * 4;
#pragma unroll
    for (int q = 0; q < 4; ++q) {
        int i = base + q;
        if (i < e) {
            int p = atomicAdd(&cur[dst[i]], 1);
            csr[p] = src[i];
        }
    }
}

// ---------------- TF32 GEMM: B fully smem-resident, A double-buffered ------
// Dynamic smem: Bf[4 tiles][4 kk][1152] + Af[2 bufs][8 mt][4 kt][128]
//   = 18432 + 8192 u32 = 106496 bytes. 2 CTAs/SM (208 KB <= 228 KB).
// A-fragment store swizzled by (kt*8) XOR to cut fill bank conflicts;
// read side compensates with the compile-time kk constant.
__device__ __forceinline__ uint32_t f2tf32(float f) {
    uint32_t u;
    asm("cvt.rna.tf32.f32 %0, %1;" : "=r"(u) : "f"(f));
    return u;
}

__global__ void __launch_bounds__(256, 2)
sgemm_tf32_kernel(const float* __restrict__ A, const float* __restrict__ B,
                  float* __restrict__ C, int M, int N, int K) {
    extern __shared__ uint32_t smemraw[];
    uint32_t* Bf = smemraw;            // (t*4 + kk) * 1152
    uint32_t* Afb = smemraw + 18432;   // buf*4096 + mt*512 + kt*128

    const int t = threadIdx.x;
    const int lane = t & 31;
    const int warp = t >> 5;
    const int brow = blockIdx.y * 128;
    const int bcol = blockIdx.x * 128;
    const int wm = (warp >> 1) * 32;
    const int wn = (warp & 1) * 64;
    const int qm = lane >> 2;
    const int qk = lane & 3;

    const int a_m0 = t >> 3;
    const int a_kg = t & 7;
    const int b_n0 = (t & 31) * 4;
    const int b_k0 = t >> 5;
    const int a_kt = a_kg >> 1;
    const int a_ik = a_kg & 1;
    const int NT = (K + 31) >> 5;      // 4 for K=100/128

    float acc[2][8][4];
#pragma unroll
    for (int mi = 0; mi < 2; ++mi)
#pragma unroll
        for (int ni = 0; ni < 8; ++ni)
#pragma unroll
            for (int q = 0; q < 4; ++q) acc[mi][ni][q] = 0.f;

    // ---- prologue: load ALL B tiles into smem (stays for whole kernel) ----
    for (int tt = 0; tt < NT; ++tt) {
#pragma unroll
        for (int it = 0; it < 4; ++it) {
            int kr = b_k0 + 8 * it;
            int gk = tt * 32 + kr;
            int gn = bcol + b_n0;
            float4 v = make_float4(0.f, 0.f, 0.f, 0.f);
            if (gk < K && gn < N)
                v = *reinterpret_cast<const float4*>(&B[(size_t)gk * N + gn]);
            uint32_t* dstp = Bf + (tt * 4 + it) * 1152;
            int qkb = b_k0 & 3;
            int slot = (b_k0 >> 2) & 1;
            float vv[4] = {v.x, v.y, v.z, v.w};
#pragma unroll
            for (int j = 0; j < 4; ++j) {
                int nn = b_n0 + j;
                int nt = nn >> 3;
                int qmb = nn & 7;
                dstp[(qmb * 4 + qkb) * 36 + nt * 2 + slot] = f2tf32(vv[j]);
            }
        }
    }

    // ---- A tile 0: global -> regs -> smem buf 0 ----
    float4 apre[4];
#pragma unroll
    for (int it = 0; it < 4; ++it) {
        int grow = brow + a_m0 + 32 * it;
        int gk = a_kg * 4;
        apre[it] = make_float4(0.f, 0.f, 0.f, 0.f);
        if (grow < M && gk < K)
            apre[it] = *reinterpret_cast<const float4*>(&A[(size_t)grow * K + gk]);
    }
    {
        uint32_t* ab = Afb + a_kt * 128;
        const int sw = a_kt * 8;
#pragma unroll
        for (int it = 0; it < 4; ++it) {
            int m = a_m0 + 32 * it;
            int mt = m >> 4;
            int qmw = m & 7;
            int idx = ((m >> 3) & 1) + 2 * a_ik;
            uint32_t* d = ab + mt * 512;
            d[(((qmw * 4 + 0) * 4 + idx)) ^ sw] = f2tf32(apre[it].x);
            d[(((qmw * 4 + 1) * 4 + idx)) ^ sw] = f2tf32(apre[it].y);
            d[(((qmw * 4 + 2) * 4 + idx)) ^ sw] = f2tf32(apre[it].z);
            d[(((qmw * 4 + 3) * 4 + idx)) ^ sw] = f2tf32(apre[it].w);
        }
    }
    __syncthreads();

    // ---- main loop: 1 sync per tile; A LDG for t+1 overlaps compute of t --
    for (int tt = 0; tt < NT; ++tt) {
        if (tt + 1 < NT) {
#pragma unroll
            for (int it = 0; it < 4; ++it) {
                int grow = brow + a_m0 + 32 * it;
                int gk = (tt + 1) * 32 + a_kg * 4;
                apre[it] = make_float4(0.f, 0.f, 0.f, 0.f);
                if (grow < M && gk < K)
                    apre[it] = *reinterpret_cast<const float4*>(&A[(size_t)grow * K + gk]);
            }
        }

        const uint32_t* Ab = Afb + (tt & 1) * 4096;
#pragma unroll
        for (int kk = 0; kk < 4; ++kk) {
            const uint32_t* abase = Ab + kk * 128 + ((lane * 4) ^ (kk * 8));
            uint32_t af[2][4];
            *reinterpret_cast<uint4*>(af[0]) =
                *reinterpret_cast<const uint4*>(abase + (wm >> 4) * 512);
            *reinterpret_cast<uint4*>(af[1]) =
                *reinterpret_cast<const uint4*>(abase + ((wm >> 4) + 1) * 512);
            uint32_t bfv[8][2];
            const uint32_t* bp = Bf + (tt * 4 + kk) * 1152 + lane * 36 + (wn >> 2);
            *reinterpret_cast<uint4*>(&bfv[0][0]) = *reinterpret_cast<const uint4*>(bp);
            *reinterpret_cast<uint4*>(&bfv[2][0]) = *reinterpret_cast<const uint4*>(bp + 4);
            *reinterpret_cast<uint4*>(&bfv[4][0]) = *reinterpret_cast<const uint4*>(bp + 8);
            *reinterpret_cast<uint4*>(&bfv[6][0]) = *reinterpret_cast<const uint4*>(bp + 12);
#pragma unroll
            for (int mi = 0; mi < 2; ++mi)
#pragma unroll
                for (int ni = 0; ni < 8; ++ni) {
                    asm volatile(
                        "mma.sync.aligned.m16n8k8.row.col.f32.tf32.tf32.f32 "
                        "{%0,%1,%2,%3}, {%4,%5,%6,%7}, {%8,%9}, {%0,%1,%2,%3};"
                        : "+f"(acc[mi][ni][0]), "+f"(acc[mi][ni][1]),
                          "+f"(acc[mi][ni][2]), "+f"(acc[mi][ni][3])
                        : "r"(af[mi][0]), "r"(af[mi][1]), "r"(af[mi][2]), "r"(af[mi][3]),
                          "r"(bfv[ni][0]), "r"(bfv[ni][1]));
                }
        }

        if (tt + 1 < NT) {
            uint32_t* ab = Afb + ((tt + 1) & 1) * 4096 + a_kt * 128;
            const int sw = a_kt * 8;
#pragma unroll
            for (int it = 0; it < 4; ++it) {
                int m = a_m0 + 32 * it;
                int mt = m >> 4;
                int qmw = m & 7;
                int idx = ((m >> 3) & 1) + 2 * a_ik;
                uint32_t* d = ab + mt * 512;
                d[(((qmw * 4 + 0) * 4 + idx)) ^ sw] = f2tf32(apre[it].x);
                d[(((qmw * 4 + 1) * 4 + idx)) ^ sw] = f2tf32(apre[it].y);
                d[(((qmw * 4 + 2) * 4 + idx)) ^ sw] = f2tf32(apre[it].z);
                d[(((qmw * 4 + 3) * 4 + idx)) ^ sw] = f2tf32(apre[it].w);
            }
        }
        __syncthreads();
    }

#pragma unroll
    for (int mi = 0; mi < 2; ++mi) {
#pragma unroll
        for (int ni = 0; ni < 8; ++ni) {
            int r0 = brow + wm + mi * 16 + qm;
            int cc = bcol + wn + ni * 8 + 2 * qk;
            if (cc + 1 < N) {
                if (r0 < M)
                    *reinterpret_cast<float2*>(&C[(size_t)r0 * N + cc]) =
                        make_float2(acc[mi][ni][0], acc[mi][ni][1]);
                if (r0 + 8 < M)
                    *reinterpret_cast<float2*>(&C[(size_t)(r0 + 8) * N + cc]) =
                        make_float2(acc[mi][ni][2], acc[mi][ni][3]);
            } else if (cc < N) {
                if (r0 < M) C[(size_t)r0 * N + cc] = acc[mi][ni][0];
                if (r0 + 8 < M) C[(size_t)(r0 + 8) * N + cc] = acc[mi][ni][2];
            }
        }
    }
}

// ---------------- GATv2 4-head edge kernel: half-warp pairs, peeled tail ---
__global__ void gat4_kernel(const float* __restrict__ xlr, int ld,
                            const float* __restrict__ att,
                            const float* __restrict__ bias,
                            const float* __restrict__ resid, int ldr,
                            const float* __restrict__ res_b,
                            const float* __restrict__ bn_g, const float* __restrict__ bn_b,
                            const float* __restrict__ bn_m, const float* __restrict__ bn_v,
                            float* __restrict__ out, int do_relu,
                            const int* __restrict__ offs, const int* __restrict__ csr,
                            int n) {
    int warp = (blockIdx.x * blockDim.x + threadIdx.x) >> 5;
    int lane = threadIdx.x & 31;
    if (warp >= n) return;
    const int i = warp;
    const int half = lane >> 4;
    const int ch = (lane & 15) * 8;

    const float* xrrow = xlr + (size_t)i * ld + 128 + ch;
    const float4 xr0 = *reinterpret_cast<const float4*>(xrrow);
    const float4 xr1 = *reinterpret_cast<const float4*>(xrrow + 4);
    const float4 at0 = *reinterpret_cast<const float4*>(att + ch);
    const float4 at1 = *reinterpret_cast<const float4*>(att + ch + 4);

    float dsum = 0.f;
    float4 acc0 = make_float4(0.f, 0.f, 0.f, 0.f);
    float4 acc1 = make_float4(0.f, 0.f, 0.f, 0.f);

    int e0 = offs[i];
    int deg = offs[i + 1] - e0;
    int tot = deg + 1;          // + implicit self-loop (index deg)
    int npair = (tot + 1) >> 1;

    int idx0 = half;
    int s0 = (idx0 < deg) ? csr[e0 + idx0] : i;
    const float* r0p = xlr + (size_t)s0 * ld + ch;
    float4 v0 = *reinterpret_cast<const float4*>(r0p);
    float4 v1 = *reinterpret_cast<const float4*>(r0p + 4);

    int k = 0;
    for (; k + 1 < npair; ++k) {
        float4 c0 = v0, c1 = v1;
        int idxn = 2 * (k + 1) + half;
        int sn = (idxn < deg) ? csr[e0 + idxn] : i;
        const float* rn = xlr + (size_t)sn * ld + ch;
        v0 = *reinterpret_cast<const float4*>(rn);
        v1 = *reinterpret_cast<const float4*>(rn + 4);
        float u, p;
        u = c0.x + xr0.x; u = fmaxf(u, 0.2f * u); p = u * at0.x;
        u = c0.y + xr0.y; u = fmaxf(u, 0.2f * u); p = fmaf(u, at0.y, p);
        u = c0.z + xr0.z; u = fmaxf(u, 0.2f * u); p = fmaf(u, at0.z, p);
        u = c0.w + xr0.w; u = fmaxf(u, 0.2f * u); p = fmaf(u, at0.w, p);
        u = c1.x + xr1.x; u = fmaxf(u, 0.2f * u); p = fmaf(u, at1.x, p);
        u = c1.y + xr1.y; u = fmaxf(u, 0.2f * u); p = fmaf(u, at1.y, p);
        u = c1.z + xr1.z; u = fmaxf(u, 0.2f * u); p = fmaf(u, at1.z, p);
        u = c1.w + xr1.w; u = fmaxf(u, 0.2f * u); p = fmaf(u, at1.w, p);
        p += __shfl_xor_sync(0xffffffffu, p, 1);
        p += __shfl_xor_sync(0xffffffffu, p, 2);
        float w = __expf(p);
        dsum += w;
        acc0.x = fmaf(w, c0.x, acc0.x);
        acc0.y = fmaf(w, c0.y, acc0.y);
        acc0.z = fmaf(w, c0.z, acc0.z);
        acc0.w = fmaf(w, c0.w, acc0.w);
        acc1.x = fmaf(w, c1.x, acc1.x);
        acc1.y = fmaf(w, c1.y, acc1.y);
        acc1.z = fmaf(w, c1.z, acc1.z);
        acc1.w = fmaf(w, c1.w, acc1.w);
    }
    {
        float4 c0 = v0, c1 = v1;
        bool valid = (2 * k + half) < tot;
        float u, p;
        u = c0.x + xr0.x; u = fmaxf(u, 0.2f * u); p = u * at0.x;
        u = c0.y + xr0.y; u = fmaxf(u, 0.2f * u); p = fmaf(u, at0.y, p);
        u = c0.z + xr0.z; u = fmaxf(u, 0.2f * u); p = fmaf(u, at0.z, p);
        u = c0.w + xr0.w; u = fmaxf(u, 0.2f * u); p = fmaf(u, at0.w, p);
        u = c1.x + xr1.x; u = fmaxf(u, 0.2f * u); p = fmaf(u, at1.x, p);
        u = c1.y + xr1.y; u = fmaxf(u, 0.2f * u); p = fmaf(u, at1.y, p);
        u = c1.z + xr1.z; u = fmaxf(u, 0.2f * u); p = fmaf(u, at1.z, p);
        u = c1.w + xr1.w; u = fmaxf(u, 0.2f * u); p = fmaf(u, at1.w, p);
        p += __shfl_xor_sync(0xffffffffu, p, 1);
        p += __shfl_xor_sync(0xffffffffu, p, 2);
        float w = valid ? __expf(p) : 0.f;
        dsum += w;
        acc0.x = fmaf(w, c0.x, acc0.x);
        acc0.y = fmaf(w, c0.y, acc0.y);
        acc0.z = fmaf(w, c0.z, acc0.z);
        acc0.w = fmaf(w, c0.w, acc0.w);
        acc1.x = fmaf(w, c1.x, acc1.x);
        acc1.y = fmaf(w, c1.y, acc1.y);
        acc1.z = fmaf(w, c1.z, acc1.z);
        acc1.w = fmaf(w, c1.w, acc1.w);
    }

    dsum += __shfl_xor_sync(0xffffffffu, dsum, 16);
    acc0.x += __shfl_xor_sync(0xffffffffu, acc0.x, 16);
    acc0.y += __shfl_xor_sync(0xffffffffu, acc0.y, 16);
    acc0.z += __shfl_xor_sync(0xffffffffu, acc0.z, 16);
    acc0.w += __shfl_xor_sync(0xffffffffu, acc0.w, 16);
    acc1.x += __shfl_xor_sync(0xffffffffu, acc1.x, 16);
    acc1.y += __shfl_xor_sync(0xffffffffu, acc1.y, 16);
    acc1.z += __shfl_xor_sync(0xffffffffu, acc1.z, 16);
    acc1.w += __shfl_xor_sync(0xffffffffu, acc1.w, 16);

    if (half == 0) {
        float inv = 1.f / dsum;
        float4 bi0 = *reinterpret_cast<const float4*>(bias + ch);
        float4 bi1 = *reinterpret_cast<const float4*>(bias + ch + 4);
        const float* rr = resid + (size_t)i * ldr + ch;
        float4 rs0 = *reinterpret_cast<const float4*>(rr);
        float4 rs1 = *reinterpret_cast<const float4*>(rr + 4);
        float4 o0, o1;
        o0.x = acc0.x * inv + bi0.x + rs0.x;
        o0.y = acc0.y * inv + bi0.y + rs0.y;
        o0.z = acc0.z * inv + bi0.z + rs0.z;
        o0.w = acc0.w * inv + bi0.w + rs0.w;
        o1.x = acc1.x * inv + bi1.x + rs1.x;
        o1.y = acc1.y * inv + bi1.y + rs1.y;
        o1.z = acc1.z * inv + bi1.z + rs1.z;
        o1.w = acc1.w * inv + bi1.w + rs1.w;
        if (res_b) {
            float4 rb0 = *reinterpret_cast<const float4*>(res_b + ch);
            float4 rb1 = *reinterpret_cast<const float4*>(res_b + ch + 4);
            o0.x += rb0.x; o0.y += rb0.y; o0.z += rb0.z; o0.w += rb0.w;
            o1.x += rb1.x; o1.y += rb1.y; o1.z += rb1.z; o1.w += rb1.w;
        }
        float4 g0 = *reinterpret_cast<const float4*>(bn_g + ch);
        float4 g1 = *reinterpret_cast<const float4*>(bn_g + ch + 4);
        float4 bb0 = *reinterpret_cast<const float4*>(bn_b + ch);
        float4 bb1 = *reinterpret_cast<const float4*>(bn_b + ch + 4);
        float4 mm0 = *reinterpret_cast<const float4*>(bn_m + ch);
        float4 mm1 = *reinterpret_cast<const float4*>(bn_m + ch + 4);
        float4 vv0 = *reinterpret_cast<const float4*>(bn_v + ch);
        float4 vv1 = *reinterpret_cast<const float4*>(bn_v + ch + 4);
        o0.x = (o0.x - mm0.x) * rsqrtf(vv0.x + 1e-5f) * g0.x + bb0.x;
        o0.y = (o0.y - mm0.y) * rsqrtf(vv0.y + 1e-5f) * g0.y + bb0.y;
        o0.z = (o0.z - mm0.z) * rsqrtf(vv0.z + 1e-5f) * g0.z + bb0.z;
        o0.w = (o0.w - mm0.w) * rsqrtf(vv0.w + 1e-5f) * g0.w + bb0.w;
        o1.x = (o1.x - mm1.x) * rsqrtf(vv1.x + 1e-5f) * g1.x + bb1.x;
        o1.y = (o1.y - mm1.y) * rsqrtf(vv1.y + 1e-5f) * g1.y + bb1.y;
        o1.z = (o1.z - mm1.z) * rsqrtf(vv1.z + 1e-5f) * g1.z + bb1.z;
        o1.w = (o1.w - mm1.w) * rsqrtf(vv1.w + 1e-5f) * g1.w + bb1.w;
        if (do_relu) {
            o0.x = fmaxf(o0.x, 0.f); o0.y = fmaxf(o0.y, 0.f);
            o0.z = fmaxf(o0.z, 0.f); o0.w = fmaxf(o0.w, 0.f);
            o1.x = fmaxf(o1.x, 0.f); o1.y = fmaxf(o1.y, 0.f);
            o1.z = fmaxf(o1.z, 0.f); o1.w = fmaxf(o1.w, 0.f);
        }
        float* orow = out + (size_t)i * 128 + ch;
        *reinterpret_cast<float4*>(orow) = o0;
        *reinterpret_cast<float4*>(orow + 4) = o1;
    }
}

// ---------------- layer-3 GAT (heads=1, ch=47): half-warp pairs ------------
__global__ void gat1_kernel(const float* __restrict__ xlr,
                            const float* __restrict__ attp,
                            const float* __restrict__ bias,
                            const float* __restrict__ res_b,
                            const float* __restrict__ bn_g, const float* __restrict__ bn_b,
                            const float* __restrict__ bn_m, const float* __restrict__ bn_v,
                            float* __restrict__ out,
                            const int* __restrict__ offs, const int* __restrict__ csr,
                            int n) {
    int warp = (blockIdx.x * blockDim.x + threadIdx.x) >> 5;
    int lane = threadIdx.x & 31;
    if (warp >= n) return;
    const int i = warp;
    const int ld = 160;
    const int half = lane >> 4;
    const int j4 = (lane & 15) * 4;

    const float4 xrv = *reinterpret_cast<const float4*>(xlr + (size_t)i * ld + 64 + j4);
    const float4 attv = *reinterpret_cast<const float4*>(attp + j4);

    float dsum = 0.f;
    float4 acc = make_float4(0.f, 0.f, 0.f, 0.f);

    int e0 = offs[i];
    int deg = offs[i + 1] - e0;
    int tot = deg + 1;
    int npair = (tot + 1) >> 1;

    int s0 = (half < deg) ? csr[e0 + half] : i;
    float4 v = *reinterpret_cast<const float4*>(xlr + (size_t)s0 * ld + j4);

    int k = 0;
    for (; k + 1 < npair; ++k) {
        float4 cur = v;
        int idxn = 2 * (k + 1) + half;
        int sn = (idxn < deg) ? csr[e0 + idxn] : i;
        v = *reinterpret_cast<const float4*>(xlr + (size_t)sn * ld + j4);
        float u, p;
        u = cur.x + xrv.x; u = fmaxf(u, 0.2f * u); p = u * attv.x;
        u = cur.y + xrv.y; u = fmaxf(u, 0.2f * u); p = fmaf(u, attv.y, p);
        u = cur.z + xrv.z; u = fmaxf(u, 0.2f * u); p = fmaf(u, attv.z, p);
        u = cur.w + xrv.w; u = fmaxf(u, 0.2f * u); p = fmaf(u, attv.w, p);
        p += __shfl_xor_sync(0xffffffffu, p, 1);
        p += __shfl_xor_sync(0xffffffffu, p, 2);
        p += __shfl_xor_sync(0xffffffffu, p, 4);
        p += __shfl_xor_sync(0xffffffffu, p, 8);
        float w = __expf(p);
        dsum += w;
        acc.x = fmaf(w, cur.x, acc.x);
        acc.y = fmaf(w, cur.y, acc.y);
        acc.z = fmaf(w, cur.z, acc.z);
        acc.w = fmaf(w, cur.w, acc.w);
    }
    {
        float4 cur = v;
        bool valid = (2 * k + half) < tot;
        float u, p;
        u = cur.x + xrv.x; u = fmaxf(u, 0.2f * u); p = u * attv.x;
        u = cur.y + xrv.y; u = fmaxf(u, 0.2f * u); p = fmaf(u, attv.y, p);
        u = cur.z + xrv.z; u = fmaxf(u, 0.2f * u); p = fmaf(u, attv.z, p);
        u = cur.w + xrv.w; u = fmaxf(u, 0.2f * u); p = fmaf(u, attv.w, p);
        p += __shfl_xor_sync(0xffffffffu, p, 1);
        p += __shfl_xor_sync(0xffffffffu, p, 2);
        p += __shfl_xor_sync(0xffffffffu, p, 4);
        p += __shfl_xor_sync(0xffffffffu, p, 8);
        float w = valid ? __expf(p) : 0.f;
        dsum += w;
        acc.x = fmaf(w, cur.x, acc.x);
        acc.y = fmaf(w, cur.y, acc.y);
        acc.z = fmaf(w, cur.z, acc.z);
        acc.w = fmaf(w, cur.w, acc.w);
    }

    dsum += __shfl_xor_sync(0xffffffffu, dsum, 16);
    acc.x += __shfl_xor_sync(0xffffffffu, acc.x, 16);
    acc.y += __shfl_xor_sync(0xffffffffu, acc.y, 16);
    acc.z += __shfl_xor_sync(0xffffffffu, acc.z, 16);
    acc.w += __shfl_xor_sync(0xffffffffu, acc.w, 16);

    if (half == 0 && j4 < 48) {
        float inv = 1.f / dsum;
        const float* resrow = xlr + (size_t)i * ld + 112;
        float a4[4] = {acc.x, acc.y, acc.z, acc.w};
#pragma unroll
        for (int q = 0; q < 4; ++q) {
            int c = j4 + q;
            if (c < 47) {
                float v2 = a4[q] * inv + bias[c] + resrow[c] + res_b[c];
                v2 = (v2 - bn_m[c]) * rsqrtf(bn_v[c] + 1e-5f) * bn_g[c] + bn_b[c];
                out[(size_t)i * 47 + c] = v2;
            }
        }
    }
}

// ---------------- host launch ---------------------------------------------
extern "C" void kernel_launch(void* const* d_in, const int* in_sizes, int n_in,
                              void* d_out, int out_size) {
    const float* x = (const float*)d_in[0];
    const int* ei = (const int*)d_in[1];
    const float* w1_src = (const float*)d_in[2];
    const float* w1_dst = (const float*)d_in[3];
    const float* att1 = (const float*)d_in[4];
    const float* b1 = (const float*)d_in[5];
    const float* bn1_g = (const float*)d_in[6];
    const float* bn1_b = (const float*)d_in[7];
    const float* bn1_m = (const float*)d_in[8];
    const float* bn1_v = (const float*)d_in[9];
    const float* res0_w = (const float*)d_in[10];
    const float* res0_b = (const float*)d_in[11];
    const float* w2_src = (const float*)d_in[12];
    const float* w2_dst = (const float*)d_in[13];
    const float* att2 = (const float*)d_in[14];
    const float* b2 = (const float*)d_in[15];
    const float* bn2_g = (const float*)d_in[16];
    const float* bn2_b = (const float*)d_in[17];
    const float* bn2_m = (const float*)d_in[18];
    const float* bn2_v = (const float*)d_in[19];
    const float* w3_src = (const float*)d_in[20];
    const float* w3_dst = (const float*)d_in[21];
    const float* att3 = (const float*)d_in[22];
    const float* b3 = (const float*)d_in[23];
    const float* bn3_g = (const float*)d_in[24];
    const float* bn3_b = (const float*)d_in[25];
    const float* bn3_m = (const float*)d_in[26];
    const float* bn3_v = (const float*)d_in[27];
    const float* res2_w = (const float*)d_in[28];
    const float* res2_b = (const float*)d_in[29];

    int n = in_sizes[0] / 100;
    int e = in_sizes[1] / 2;
    if (n > NN) n = NN;
    if (e > EE) e = EE;
    const int* srcp = ei;
    const int* dstp = ei + e;

    float *g1, *h1, *g2, *h2, *g3, *w1b, *w2b, *w3b, *att3p;
    int *cnt, *offs, *cur, *csr, *bsum, *boff;
    cudaGetSymbolAddress((void**)&g1, g_g1);
    cudaGetSymbolAddress((void**)&h1, g_h1);
    cudaGetSymbolAddress((void**)&g2, g_g2);
    cudaGetSymbolAddress((void**)&h2, g_h2);
    cudaGetSymbolAddress((void**)&g3, g_g3);
    cudaGetSymbolAddress((void**)&w1b, g_w1);
    cudaGetSymbolAddress((void**)&w2b, g_w2);
    cudaGetSymbolAddress((void**)&w3b, g_w3);
    cudaGetSymbolAddress((void**)&att3p, g_att3p);
    cudaGetSymbolAddress((void**)&cnt, g_cnt);
    cudaGetSymbolAddress((void**)&offs, g_offs);
    cudaGetSymbolAddress((void**)&cur, g_cur);
    cudaGetSymbolAddress((void**)&csr, g_csr);
    cudaGetSymbolAddress((void**)&bsum, g_bsum);
    cudaGetSymbolAddress((void**)&boff, g_boff);

    int gatBlocks = (n + 7) / 8;
    int rowsB = (n + 127) / 128;
    int edgeBlocks = (e + 1023) / 1024;
    int scanBlocks = (n + 255) / 256;

    const int GEMM_SMEM = (4 * 4 * 1152 + 2 * 8 * 4 * 128) * 4;  // 106496 B
    cudaFuncSetAttribute(sgemm_tf32_kernel,
                         cudaFuncAttributeMaxDynamicSharedMemorySize, GEMM_SMEM);

    prep_kernel<<<148, 256>>>(w1_src, w1_dst, res0_w, w2_src, w2_dst,
                              w3_src, w3_dst, res2_w, att3,
                              w1b, w2b, w3b, att3p, cnt, n);
    hist_kernel<<<edgeBlocks, 256>>>(dstp, cnt, e);
    scanA_kernel<<<scanBlocks, 256>>>(cnt, bsum, n);
    scanB_kernel<<<1, 256>>>(bsum, boff, scanBlocks);
    scanC_kernel<<<scanBlocks, 256>>>(cnt, boff, offs, cur, n);
    scatter_kernel<<<edgeBlocks, 256>>>(srcp, dstp, cur, csr, e);
    sgemm_tf32_kernel<<<dim3(3, rowsB), 256, GEMM_SMEM>>>(x, w1b, g1, n, 384, 100);

    // ----- layer 1 -----
    gat4_kernel<<<gatBlocks, 256>>>(g1, 384, att1, b1,
                                    g1 + 256, 384, res0_b,
                                    bn1_g, bn1_b, bn1_m, bn1_v,
                                    h1, 1, offs, csr, n);

    // ----- layer 2 -----
    sgemm_tf32_kernel<<<dim3(2, rowsB), 256, GEMM_SMEM>>>(h1, w2b, g2, n, 256, 128);
    gat4_kernel<<<gatBlocks, 256>>>(g2, 256, att2, b2,
                                    h1, 128, nullptr,
                                    bn2_g, bn2_b, bn2_m, bn2_v,
                                    h2, 1, offs, csr, n);

    // ----- layer 3 -----
    sgemm_tf32_kernel<<<dim3(2, rowsB), 256, GEMM_SMEM>>>(h2, w3b, g3, n, 160, 128);
    gat1_kernel<<<gatBlocks, 256>>>(g3, att3p, b3, res2_b,
                                    bn3_g, bn3_b, bn3_m, bn3_v,
                                    (float*)d_out, offs, csr, n);
}

// round 17
// speedup vs baseline: 1.2053x; 1.0132x over previous
#include <cuda_runtime.h>
#include <math.h>
#include <stdint.h>

// Problem constants (fixed by the dataset)
#define NN 50000
#define EE 800000

// ---------------- scratch (static device globals; no allocation) ----------
__device__ float g_g1[(size_t)NN * 384];  // [xl1 | xr1 | res1]
__device__ float g_h1[(size_t)NN * 128];
__device__ float g_g2[(size_t)NN * 256];  // [xl2 | xr2]
__device__ float g_h2[(size_t)NN * 128];
__device__ float g_g3[(size_t)NN * 160];  // [xl3:64 | xr3:48 | res3:48]
__device__ float g_w1[100 * 384];
__device__ float g_w2[128 * 256];
__device__ float g_w3[128 * 160];
__device__ float g_att3p[128];
__device__ int g_cnt[NN];
__device__ int g_offs[NN + 1];
__device__ int g_cur[NN];
__device__ int g_csr[EE];
__device__ int g_bsum[256];
__device__ int g_boff[256];

// ---------------- prep: pack w1/w2/w3 + pad att3 (no cnt here) ------------
__global__ void prep_kernel(const float* __restrict__ w1_src, const float* __restrict__ w1_dst,
                            const float* __restrict__ res0_w,
                            const float* __restrict__ w2_src, const float* __restrict__ w2_dst,
                            const float* __restrict__ w3_src, const float* __restrict__ w3_dst,
                            const float* __restrict__ res2_w,
                            const float* __restrict__ att3,
                            float* __restrict__ w1b, float* __restrict__ w2b,
                            float* __restrict__ w3b, float* __restrict__ att3p) {
    const int W1T = 100 * 384;
    const int W2T = 128 * 256;
    const int W3T = 128 * 160;
    int total = W1T + W2T + W3T + 128;
    for (int idx = blockIdx.x * blockDim.x + threadIdx.x; idx < total;
         idx += gridDim.x * blockDim.x) {
        int r = idx;
        if (r < W1T) {
            int k = r / 384, col = r - k * 384;
            float v;
            if (col < 128) v = w1_src[k * 128 + col];
            else if (col < 256) v = w1_dst[k * 128 + col - 128];
            else v = res0_w[k * 128 + col - 256];
            w1b[r] = v;
            continue;
        }
        r -= W1T;
        if (r < W2T) {
            int k = r >> 8, col = r & 255;
            w2b[r] = (col < 128) ? w2_src[k * 128 + col] : w2_dst[k * 128 + col - 128];
            continue;
        }
        r -= W2T;
        if (r < W3T) {
            int k = r / 160, col = r - k * 160;
            float v = 0.f;
            if (col < 64) { if (col < 47) v = w3_src[k * 47 + col]; }
            else if (col < 112) { int c = col - 64; if (c < 47) v = w3_dst[k * 47 + c]; }
            else { int c = col - 112; if (c < 47) v = res2_w[k * 47 + c]; }
            w3b[r] = v;
            continue;
        }
        r -= W3T;
        att3p[r] = (r < 47) ? att3[r] : 0.f;
    }
}

__global__ void zeroc_kernel(int* __restrict__ a, int m) {
    int t = blockIdx.x * blockDim.x + threadIdx.x;
    if (t < m) a[t] = 0;
}

// ---------------- CSR construction (4 edges/thread for MLP) ----------------
__global__ void hist_kernel(const int* __restrict__ dst, int* __restrict__ cnt, int e) {
    int base = (blockIdx.x * blockDim.x + threadIdx.x) * 4;
#pragma unroll
    for (int q = 0; q < 4; ++q) {
        int i = base + q;
        if (i < e) atomicAdd(&cnt[dst[i]], 1);
    }
}

__global__ void scanA_kernel(const int* __restrict__ cnt, int* __restrict__ bsum, int n) {
    __shared__ int sh[256];
    int t = threadIdx.x;
    int i = blockIdx.x * 256 + t;
    sh[t] = (i < n) ? cnt[i] : 0;
    __syncthreads();
    for (int off = 128; off > 0; off >>= 1) {
        if (t < off) sh[t] += sh[t + off];
        __syncthreads();
    }
    if (t == 0) bsum[blockIdx.x] = sh[0];
}

__global__ void scanB_kernel(const int* __restrict__ bsum, int* __restrict__ boff, int nb) {
    __shared__ int sh[256];
    int t = threadIdx.x;
    int v = (t < nb) ? bsum[t] : 0;
    sh[t] = v;
    __syncthreads();
    for (int off = 1; off < 256; off <<= 1) {
        int u = (t >= off) ? sh[t - off] : 0;
        __syncthreads();
        sh[t] += u;
        __syncthreads();
    }
    if (t < nb) boff[t] = sh[t] - v;  // exclusive
}

__global__ void scanC_kernel(const int* __restrict__ cnt, const int* __restrict__ boff,
                             int* __restrict__ offs, int* __restrict__ cur, int n) {
    __shared__ int sh[256];
    int t = threadIdx.x;
    int i = blockIdx.x * 256 + t;
    int v = (i < n) ? cnt[i] : 0;
    sh[t] = v;
    __syncthreads();
    for (int off = 1; off < 256; off <<= 1) {
        int u = (t >= off) ? sh[t - off] : 0;
        __syncthreads();
        sh[t] += u;
        __syncthreads();
    }
    int o = boff[blockIdx.x] + sh[t] - v;  // exclusive prefix
    if (i <= n) offs[i] = o;               // i == n -> total (pad cnt = 0)
    if (i < n) cur[i] = o;
}

__global__ void scatter_kernel(const int* __restrict__ src, const int* __restrict__ dst,
                               int* __restrict__ cur, int* __restrict__ csr, int e) {
    int base = (blockIdx.x * blockDim.x + threadIdx.x) * 4;
#pragma unroll
    for (int q = 0; q < 4; ++q) {
        int i = base + q;
        if (i < e) {
            int p = atomicAdd(&cur[dst[i]], 1);
            csr[p] = src[i];
        }
    }
}

// ---------------- TF32 GEMM: B fully smem-resident, A double-buffered ------
__device__ __forceinline__ uint32_t f2tf32(float f) {
    uint32_t u;
    asm("cvt.rna.tf32.f32 %0, %1;" : "=r"(u) : "f"(f));
    return u;
}

__global__ void __launch_bounds__(256, 2)
sgemm_tf32_kernel(const float* __restrict__ A, const float* __restrict__ B,
                  float* __restrict__ C, int M, int N, int K) {
    extern __shared__ uint32_t smemraw[];
    uint32_t* Bf = smemraw;            // (t*4 + kk) * 1152
    uint32_t* Afb = smemraw + 18432;   // buf*4096 + mt*512 + kt*128

    const int t = threadIdx.x;
    const int lane = t & 31;
    const int warp = t >> 5;
    const int brow = blockIdx.y * 128;
    const int bcol = blockIdx.x * 128;
    const int wm = (warp >> 1) * 32;
    const int wn = (warp & 1) * 64;
    const int qm = lane >> 2;
    const int qk = lane & 3;

    const int a_m0 = t >> 3;
    const int a_kg = t & 7;
    const int b_n0 = (t & 31) * 4;
    const int b_k0 = t >> 5;
    const int a_kt = a_kg >> 1;
    const int a_ik = a_kg & 1;
    const int NT = (K + 31) >> 5;

    float acc[2][8][4];
#pragma unroll
    for (int mi = 0; mi < 2; ++mi)
#pragma unroll
        for (int ni = 0; ni < 8; ++ni)
#pragma unroll
            for (int q = 0; q < 4; ++q) acc[mi][ni][q] = 0.f;

    for (int tt = 0; tt < NT; ++tt) {
#pragma unroll
        for (int it = 0; it < 4; ++it) {
            int kr = b_k0 + 8 * it;
            int gk = tt * 32 + kr;
            int gn = bcol + b_n0;
            float4 v = make_float4(0.f, 0.f, 0.f, 0.f);
            if (gk < K && gn < N)
                v = *reinterpret_cast<const float4*>(&B[(size_t)gk * N + gn]);
            uint32_t* dstp = Bf + (tt * 4 + it) * 1152;
            int qkb = b_k0 & 3;
            int slot = (b_k0 >> 2) & 1;
            float vv[4] = {v.x, v.y, v.z, v.w};
#pragma unroll
            for (int j = 0; j < 4; ++j) {
                int nn = b_n0 + j;
                int nt = nn >> 3;
                int qmb = nn & 7;
                dstp[(qmb * 4 + qkb) * 36 + nt * 2 + slot] = f2tf32(vv[j]);
            }
        }
    }

    float4 apre[4];
#pragma unroll
    for (int it = 0; it < 4; ++it) {
        int grow = brow + a_m0 + 32 * it;
        int gk = a_kg * 4;
        apre[it] = make_float4(0.f, 0.f, 0.f, 0.f);
        if (grow < M && gk < K)
            apre[it] = *reinterpret_cast<const float4*>(&A[(size_t)grow * K + gk]);
    }
    {
        uint32_t* ab = Afb + a_kt * 128;
        const int sw = a_kt * 8;
#pragma unroll
        for (int it = 0; it < 4; ++it) {
            int m = a_m0 + 32 * it;
            int mt = m >> 4;
            int qmw = m & 7;
            int idx = ((m >> 3) & 1) + 2 * a_ik;
            uint32_t* d = ab + mt * 512;
            d[(((qmw * 4 + 0) * 4 + idx)) ^ sw] = f2tf32(apre[it].x);
            d[(((qmw * 4 + 1) * 4 + idx)) ^ sw] = f2tf32(apre[it].y);
            d[(((qmw * 4 + 2) * 4 + idx)) ^ sw] = f2tf32(apre[it].z);
            d[(((qmw * 4 + 3) * 4 + idx)) ^ sw] = f2tf32(apre[it].w);
        }
    }
    __syncthreads();

    for (int tt = 0; tt < NT; ++tt) {
        if (tt + 1 < NT) {
#pragma unroll
            for (int it = 0; it < 4; ++it) {
                int grow = brow + a_m0 + 32 * it;
                int gk = (tt + 1) * 32 + a_kg * 4;
                apre[it] = make_float4(0.f, 0.f, 0.f, 0.f);
                if (grow < M && gk < K)
                    apre[it] = *reinterpret_cast<const float4*>(&A[(size_t)grow * K + gk]);
            }
        }

        const uint32_t* Ab = Afb + (tt & 1) * 4096;
#pragma unroll
        for (int kk = 0; kk < 4; ++kk) {
            const uint32_t* abase = Ab + kk * 128 + ((lane * 4) ^ (kk * 8));
            uint32_t af[2][4];
            *reinterpret_cast<uint4*>(af[0]) =
                *reinterpret_cast<const uint4*>(abase + (wm >> 4) * 512);
            *reinterpret_cast<uint4*>(af[1]) =
                *reinterpret_cast<const uint4*>(abase + ((wm >> 4) + 1) * 512);
            uint32_t bfv[8][2];
            const uint32_t* bp = Bf + (tt * 4 + kk) * 1152 + lane * 36 + (wn >> 2);
            *reinterpret_cast<uint4*>(&bfv[0][0]) = *reinterpret_cast<const uint4*>(bp);
            *reinterpret_cast<uint4*>(&bfv[2][0]) = *reinterpret_cast<const uint4*>(bp + 4);
            *reinterpret_cast<uint4*>(&bfv[4][0]) = *reinterpret_cast<const uint4*>(bp + 8);
            *reinterpret_cast<uint4*>(&bfv[6][0]) = *reinterpret_cast<const uint4*>(bp + 12);
#pragma unroll
            for (int mi = 0; mi < 2; ++mi)
#pragma unroll
                for (int ni = 0; ni < 8; ++ni) {
                    asm volatile(
                        "mma.sync.aligned.m16n8k8.row.col.f32.tf32.tf32.f32 "
                        "{%0,%1,%2,%3}, {%4,%5,%6,%7}, {%8,%9}, {%0,%1,%2,%3};"
                        : "+f"(acc[mi][ni][0]), "+f"(acc[mi][ni][1]),
                          "+f"(acc[mi][ni][2]), "+f"(acc[mi][ni][3])
                        : "r"(af[mi][0]), "r"(af[mi][1]), "r"(af[mi][2]), "r"(af[mi][3]),
                          "r"(bfv[ni][0]), "r"(bfv[ni][1]));
                }
        }

        if (tt + 1 < NT) {
            uint32_t* ab = Afb + ((tt + 1) & 1) * 4096 + a_kt * 128;
            const int sw = a_kt * 8;
#pragma unroll
            for (int it = 0; it < 4; ++it) {
                int m = a_m0 + 32 * it;
                int mt = m >> 4;
                int qmw = m & 7;
                int idx = ((m >> 3) & 1) + 2 * a_ik;
                uint32_t* d = ab + mt * 512;
                d[(((qmw * 4 + 0) * 4 + idx)) ^ sw] = f2tf32(apre[it].x);
                d[(((qmw * 4 + 1) * 4 + idx)) ^ sw] = f2tf32(apre[it].y);
                d[(((qmw * 4 + 2) * 4 + idx)) ^ sw] = f2tf32(apre[it].z);
                d[(((qmw * 4 + 3) * 4 + idx)) ^ sw] = f2tf32(apre[it].w);
            }
        }
        __syncthreads();
    }

#pragma unroll
    for (int mi = 0; mi < 2; ++mi) {
#pragma unroll
        for (int ni = 0; ni < 8; ++ni) {
            int r0 = brow + wm + mi * 16 + qm;
            int cc = bcol + wn + ni * 8 + 2 * qk;
            if (cc + 1 < N) {
                if (r0 < M)
                    *reinterpret_cast<float2*>(&C[(size_t)r0 * N + cc]) =
                        make_float2(acc[mi][ni][0], acc[mi][ni][1]);
                if (r0 + 8 < M)
                    *reinterpret_cast<float2*>(&C[(size_t)(r0 + 8) * N + cc]) =
                        make_float2(acc[mi][ni][2], acc[mi][ni][3]);
            } else if (cc < N) {
                if (r0 < M) C[(size_t)r0 * N + cc] = acc[mi][ni][0];
                if (r0 + 8 < M) C[(size_t)(r0 + 8) * N + cc] = acc[mi][ni][2];
            }
        }
    }
}

// ---------------- GATv2 4-head edge kernel: half-warp pairs, peeled tail ---
__global__ void gat4_kernel(const float* __restrict__ xlr, int ld,
                            const float* __restrict__ att,
                            const float* __restrict__ bias,
                            const float* __restrict__ resid, int ldr,
                            const float* __restrict__ res_b,
                            const float* __restrict__ bn_g, const float* __restrict__ bn_b,
                            const float* __restrict__ bn_m, const float* __restrict__ bn_v,
                            float* __restrict__ out, int do_relu,
                            const int* __restrict__ offs, const int* __restrict__ csr,
                            int n) {
    int warp = (blockIdx.x * blockDim.x + threadIdx.x) >> 5;
    int lane = threadIdx.x & 31;
    if (warp >= n) return;
    const int i = warp;
    const int half = lane >> 4;
    const int ch = (lane & 15) * 8;

    const float* xrrow = xlr + (size_t)i * ld + 128 + ch;
    const float4 xr0 = *reinterpret_cast<const float4*>(xrrow);
    const float4 xr1 = *reinterpret_cast<const float4*>(xrrow + 4);
    const float4 at0 = *reinterpret_cast<const float4*>(att + ch);
    const float4 at1 = *reinterpret_cast<const float4*>(att + ch + 4);

    float dsum = 0.f;
    float4 acc0 = make_float4(0.f, 0.f, 0.f, 0.f);
    float4 acc1 = make_float4(0.f, 0.f, 0.f, 0.f);

    int e0 = offs[i];
    int deg = offs[i + 1] - e0;
    int tot = deg + 1;
    int npair = (tot + 1) >> 1;

    int idx0 = half;
    int s0 = (idx0 < deg) ? csr[e0 + idx0] : i;
    const float* r0p = xlr + (size_t)s0 * ld + ch;
    float4 v0 = *reinterpret_cast<const float4*>(r0p);
    float4 v1 = *reinterpret_cast<const float4*>(r0p + 4);

    int k = 0;
    for (; k + 1 < npair; ++k) {
        float4 c0 = v0, c1 = v1;
        int idxn = 2 * (k + 1) + half;
        int sn = (idxn < deg) ? csr[e0 + idxn] : i;
        const float* rn = xlr + (size_t)sn * ld + ch;
        v0 = *reinterpret_cast<const float4*>(rn);
        v1 = *reinterpret_cast<const float4*>(rn + 4);
        float u, p;
        u = c0.x + xr0.x; u = fmaxf(u, 0.2f * u); p = u * at0.x;
        u = c0.y + xr0.y; u = fmaxf(u, 0.2f * u); p = fmaf(u, at0.y, p);
        u = c0.z + xr0.z; u = fmaxf(u, 0.2f * u); p = fmaf(u, at0.z, p);
        u = c0.w + xr0.w; u = fmaxf(u, 0.2f * u); p = fmaf(u, at0.w, p);
        u = c1.x + xr1.x; u = fmaxf(u, 0.2f * u); p = fmaf(u, at1.x, p);
        u = c1.y + xr1.y; u = fmaxf(u, 0.2f * u); p = fmaf(u, at1.y, p);
        u = c1.z + xr1.z; u = fmaxf(u, 0.2f * u); p = fmaf(u, at1.z, p);
        u = c1.w + xr1.w; u = fmaxf(u, 0.2f * u); p = fmaf(u, at1.w, p);
        p += __shfl_xor_sync(0xffffffffu, p, 1);
        p += __shfl_xor_sync(0xffffffffu, p, 2);
        float w = __expf(p);
        dsum += w;
        acc0.x = fmaf(w, c0.x, acc0.x);
        acc0.y = fmaf(w, c0.y, acc0.y);
        acc0.z = fmaf(w, c0.z, acc0.z);
        acc0.w = fmaf(w, c0.w, acc0.w);
        acc1.x = fmaf(w, c1.x, acc1.x);
        acc1.y = fmaf(w, c1.y, acc1.y);
        acc1.z = fmaf(w, c1.z, acc1.z);
        acc1.w = fmaf(w, c1.w, acc1.w);
    }
    {
        float4 c0 = v0, c1 = v1;
        bool valid = (2 * k + half) < tot;
        float u, p;
        u = c0.x + xr0.x; u = fmaxf(u, 0.2f * u); p = u * at0.x;
        u = c0.y + xr0.y; u = fmaxf(u, 0.2f * u); p = fmaf(u, at0.y, p);
        u = c0.z + xr0.z; u = fmaxf(u, 0.2f * u); p = fmaf(u, at0.z, p);
        u = c0.w + xr0.w; u = fmaxf(u, 0.2f * u); p = fmaf(u, at0.w, p);
        u = c1.x + xr1.x; u = fmaxf(u, 0.2f * u); p = fmaf(u, at1.x, p);
        u = c1.y + xr1.y; u = fmaxf(u, 0.2f * u); p = fmaf(u, at1.y, p);
        u = c1.z + xr1.z; u = fmaxf(u, 0.2f * u); p = fmaf(u, at1.z, p);
        u = c1.w + xr1.w; u = fmaxf(u, 0.2f * u); p = fmaf(u, at1.w, p);
        p += __shfl_xor_sync(0xffffffffu, p, 1);
        p += __shfl_xor_sync(0xffffffffu, p, 2);
        float w = valid ? __expf(p) : 0.f;
        dsum += w;
        acc0.x = fmaf(w, c0.x, acc0.x);
        acc0.y = fmaf(w, c0.y, acc0.y);
        acc0.z = fmaf(w, c0.z, acc0.z);
        acc0.w = fmaf(w, c0.w, acc0.w);
        acc1.x = fmaf(w, c1.x, acc1.x);
        acc1.y = fmaf(w, c1.y, acc1.y);
        acc1.z = fmaf(w, c1.z, acc1.z);
        acc1.w = fmaf(w, c1.w, acc1.w);
    }

    dsum += __shfl_xor_sync(0xffffffffu, dsum, 16);
    acc0.x += __shfl_xor_sync(0xffffffffu, acc0.x, 16);
    acc0.y += __shfl_xor_sync(0xffffffffu, acc0.y, 16);
    acc0.z += __shfl_xor_sync(0xffffffffu, acc0.z, 16);
    acc0.w += __shfl_xor_sync(0xffffffffu, acc0.w, 16);
    acc1.x += __shfl_xor_sync(0xffffffffu, acc1.x, 16);
    acc1.y += __shfl_xor_sync(0xffffffffu, acc1.y, 16);
    acc1.z += __shfl_xor_sync(0xffffffffu, acc1.z, 16);
    acc1.w += __shfl_xor_sync(0xffffffffu, acc1.w, 16);

    if (half == 0) {
        float inv = 1.f / dsum;
        float4 bi0 = *reinterpret_cast<const float4*>(bias + ch);
        float4 bi1 = *reinterpret_cast<const float4*>(bias + ch + 4);
        const float* rr = resid + (size_t)i * ldr + ch;
        float4 rs0 = *reinterpret_cast<const float4*>(rr);
        float4 rs1 = *reinterpret_cast<const float4*>(rr + 4);
        float4 o0, o1;
        o0.x = acc0.x * inv + bi0.x + rs0.x;
        o0.y = acc0.y * inv + bi0.y + rs0.y;
        o0.z = acc0.z * inv + bi0.z + rs0.z;
        o0.w = acc0.w * inv + bi0.w + rs0.w;
        o1.x = acc1.x * inv + bi1.x + rs1.x;
        o1.y = acc1.y * inv + bi1.y + rs1.y;
        o1.z = acc1.z * inv + bi1.z + rs1.z;
        o1.w = acc1.w * inv + bi1.w + rs1.w;
        if (res_b) {
            float4 rb0 = *reinterpret_cast<const float4*>(res_b + ch);
            float4 rb1 = *reinterpret_cast<const float4*>(res_b + ch + 4);
            o0.x += rb0.x; o0.y += rb0.y; o0.z += rb0.z; o0.w += rb0.w;
            o1.x += rb1.x; o1.y += rb1.y; o1.z += rb1.z; o1.w += rb1.w;
        }
        float4 g0 = *reinterpret_cast<const float4*>(bn_g + ch);
        float4 g1 = *reinterpret_cast<const float4*>(bn_g + ch + 4);
        float4 bb0 = *reinterpret_cast<const float4*>(bn_b + ch);
        float4 bb1 = *reinterpret_cast<const float4*>(bn_b + ch + 4);
        float4 mm0 = *reinterpret_cast<const float4*>(bn_m + ch);
        float4 mm1 = *reinterpret_cast<const float4*>(bn_m + ch + 4);
        float4 vv0 = *reinterpret_cast<const float4*>(bn_v + ch);
        float4 vv1 = *reinterpret_cast<const float4*>(bn_v + ch + 4);
        o0.x = (o0.x - mm0.x) * rsqrtf(vv0.x + 1e-5f) * g0.x + bb0.x;
        o0.y = (o0.y - mm0.y) * rsqrtf(vv0.y + 1e-5f) * g0.y + bb0.y;
        o0.z = (o0.z - mm0.z) * rsqrtf(vv0.z + 1e-5f) * g0.z + bb0.z;
        o0.w = (o0.w - mm0.w) * rsqrtf(vv0.w + 1e-5f) * g0.w + bb0.w;
        o1.x = (o1.x - mm1.x) * rsqrtf(vv1.x + 1e-5f) * g1.x + bb1.x;
        o1.y = (o1.y - mm1.y) * rsqrtf(vv1.y + 1e-5f) * g1.y + bb1.y;
        o1.z = (o1.z - mm1.z) * rsqrtf(vv1.z + 1e-5f) * g1.z + bb1.z;
        o1.w = (o1.w - mm1.w) * rsqrtf(vv1.w + 1e-5f) * g1.w + bb1.w;
        if (do_relu) {
            o0.x = fmaxf(o0.x, 0.f); o0.y = fmaxf(o0.y, 0.f);
            o0.z = fmaxf(o0.z, 0.f); o0.w = fmaxf(o0.w, 0.f);
            o1.x = fmaxf(o1.x, 0.f); o1.y = fmaxf(o1.y, 0.f);
            o1.z = fmaxf(o1.z, 0.f); o1.w = fmaxf(o1.w, 0.f);
        }
        float* orow = out + (size_t)i * 128 + ch;
        *reinterpret_cast<float4*>(orow) = o0;
        *reinterpret_cast<float4*>(orow + 4) = o1;
    }
}

// ---------------- layer-3 GAT (heads=1, ch=47): half-warp pairs ------------
__global__ void gat1_kernel(const float* __restrict__ xlr,
                            const float* __restrict__ attp,
                            const float* __restrict__ bias,
                            const float* __restrict__ res_b,
                            const float* __restrict__ bn_g, const float* __restrict__ bn_b,
                            const float* __restrict__ bn_m, const float* __restrict__ bn_v,
                            float* __restrict__ out,
                            const int* __restrict__ offs, const int* __restrict__ csr,
                            int n) {
    int warp = (blockIdx.x * blockDim.x + threadIdx.x) >> 5;
    int lane = threadIdx.x & 31;
    if (warp >= n) return;
    const int i = warp;
    const int ld = 160;
    const int half = lane >> 4;
    const int j4 = (lane & 15) * 4;

    const float4 xrv = *reinterpret_cast<const float4*>(xlr + (size_t)i * ld + 64 + j4);
    const float4 attv = *reinterpret_cast<const float4*>(attp + j4);

    float dsum = 0.f;
    float4 acc = make_float4(0.f, 0.f, 0.f, 0.f);

    int e0 = offs[i];
    int deg = offs[i + 1] - e0;
    int tot = deg + 1;
    int npair = (tot + 1) >> 1;

    int s0 = (half < deg) ? csr[e0 + half] : i;
    float4 v = *reinterpret_cast<const float4*>(xlr + (size_t)s0 * ld + j4);

    int k = 0;
    for (; k + 1 < npair; ++k) {
        float4 cur = v;
        int idxn = 2 * (k + 1) + half;
        int sn = (idxn < deg) ? csr[e0 + idxn] : i;
        v = *reinterpret_cast<const float4*>(xlr + (size_t)sn * ld + j4);
        float u, p;
        u = cur.x + xrv.x; u = fmaxf(u, 0.2f * u); p = u * attv.x;
        u = cur.y + xrv.y; u = fmaxf(u, 0.2f * u); p = fmaf(u, attv.y, p);
        u = cur.z + xrv.z; u = fmaxf(u, 0.2f * u); p = fmaf(u, attv.z, p);
        u = cur.w + xrv.w; u = fmaxf(u, 0.2f * u); p = fmaf(u, attv.w, p);
        p += __shfl_xor_sync(0xffffffffu, p, 1);
        p += __shfl_xor_sync(0xffffffffu, p, 2);
        p += __shfl_xor_sync(0xffffffffu, p, 4);
        p += __shfl_xor_sync(0xffffffffu, p, 8);
        float w = __expf(p);
        dsum += w;
        acc.x = fmaf(w, cur.x, acc.x);
        acc.y = fmaf(w, cur.y, acc.y);
        acc.z = fmaf(w, cur.z, acc.z);
        acc.w = fmaf(w, cur.w, acc.w);
    }
    {
        float4 cur = v;
        bool valid = (2 * k + half) < tot;
        float u, p;
        u = cur.x + xrv.x; u = fmaxf(u, 0.2f * u); p = u * attv.x;
        u = cur.y + xrv.y; u = fmaxf(u, 0.2f * u); p = fmaf(u, attv.y, p);
        u = cur.z + xrv.z; u = fmaxf(u, 0.2f * u); p = fmaf(u, attv.z, p);
        u = cur.w + xrv.w; u = fmaxf(u, 0.2f * u); p = fmaf(u, attv.w, p);
        p += __shfl_xor_sync(0xffffffffu, p, 1);
        p += __shfl_xor_sync(0xffffffffu, p, 2);
        p += __shfl_xor_sync(0xffffffffu, p, 4);
        p += __shfl_xor_sync(0xffffffffu, p, 8);
        float w = valid ? __expf(p) : 0.f;
        dsum += w;
        acc.x = fmaf(w, cur.x, acc.x);
        acc.y = fmaf(w, cur.y, acc.y);
        acc.z = fmaf(w, cur.z, acc.z);
        acc.w = fmaf(w, cur.w, acc.w);
    }

    dsum += __shfl_xor_sync(0xffffffffu, dsum, 16);
    acc.x += __shfl_xor_sync(0xffffffffu, acc.x, 16);
    acc.y += __shfl_xor_sync(0xffffffffu, acc.y, 16);
    acc.z += __shfl_xor_sync(0xffffffffu, acc.z, 16);
    acc.w += __shfl_xor_sync(0xffffffffu, acc.w, 16);

    if (half == 0 && j4 < 48) {
        float inv = 1.f / dsum;
        const float* resrow = xlr + (size_t)i * ld + 112;
        float a4[4] = {acc.x, acc.y, acc.z, acc.w};
#pragma unroll
        for (int q = 0; q < 4; ++q) {
            int c = j4 + q;
            if (c < 47) {
                float v2 = a4[q] * inv + bias[c] + resrow[c] + res_b[c];
                v2 = (v2 - bn_m[c]) * rsqrtf(bn_v[c] + 1e-5f) * bn_g[c] + bn_b[c];
                out[(size_t)i * 47 + c] = v2;
            }
        }
    }
}

// ---------------- host launch ---------------------------------------------
extern "C" void kernel_launch(void* const* d_in, const int* in_sizes, int n_in,
                              void* d_out, int out_size) {
    const float* x = (const float*)d_in[0];
    const int* ei = (const int*)d_in[1];
    const float* w1_src = (const float*)d_in[2];
    const float* w1_dst = (const float*)d_in[3];
    const float* att1 = (const float*)d_in[4];
    const float* b1 = (const float*)d_in[5];
    const float* bn1_g = (const float*)d_in[6];
    const float* bn1_b = (const float*)d_in[7];
    const float* bn1_m = (const float*)d_in[8];
    const float* bn1_v = (const float*)d_in[9];
    const float* res0_w = (const float*)d_in[10];
    const float* res0_b = (const float*)d_in[11];
    const float* w2_src = (const float*)d_in[12];
    const float* w2_dst = (const float*)d_in[13];
    const float* att2 = (const float*)d_in[14];
    const float* b2 = (const float*)d_in[15];
    const float* bn2_g = (const float*)d_in[16];
    const float* bn2_b = (const float*)d_in[17];
    const float* bn2_m = (const float*)d_in[18];
    const float* bn2_v = (const float*)d_in[19];
    const float* w3_src = (const float*)d_in[20];
    const float* w3_dst = (const float*)d_in[21];
    const float* att3 = (const float*)d_in[22];
    const float* b3 = (const float*)d_in[23];
    const float* bn3_g = (const float*)d_in[24];
    const float* bn3_b = (const float*)d_in[25];
    const float* bn3_m = (const float*)d_in[26];
    const float* bn3_v = (const float*)d_in[27];
    const float* res2_w = (const float*)d_in[28];
    const float* res2_b = (const float*)d_in[29];

    int n = in_sizes[0] / 100;
    int e = in_sizes[1] / 2;
    if (n > NN) n = NN;
    if (e > EE) e = EE;
    const int* srcp = ei;
    const int* dstp = ei + e;

    float *g1, *h1, *g2, *h2, *g3, *w1b, *w2b, *w3b, *att3p;
    int *cnt, *offs, *cur, *csr, *bsum, *boff;
    cudaGetSymbolAddress((void**)&g1, g_g1);
    cudaGetSymbolAddress((void**)&h1, g_h1);
    cudaGetSymbolAddress((void**)&g2, g_g2);
    cudaGetSymbolAddress((void**)&h2, g_h2);
    cudaGetSymbolAddress((void**)&g3, g_g3);
    cudaGetSymbolAddress((void**)&w1b, g_w1);
    cudaGetSymbolAddress((void**)&w2b, g_w2);
    cudaGetSymbolAddress((void**)&w3b, g_w3);
    cudaGetSymbolAddress((void**)&att3p, g_att3p);
    cudaGetSymbolAddress((void**)&cnt, g_cnt);
    cudaGetSymbolAddress((void**)&offs, g_offs);
    cudaGetSymbolAddress((void**)&cur, g_cur);
    cudaGetSymbolAddress((void**)&csr, g_csr);
    cudaGetSymbolAddress((void**)&bsum, g_bsum);
    cudaGetSymbolAddress((void**)&boff, g_boff);

    int gatBlocks = (n + 7) / 8;
    int rowsB = (n + 127) / 128;
    int edgeBlocks = (e + 1023) / 1024;
    int scanBlocks = (n + 255) / 256;

    const int GEMM_SMEM = (4 * 4 * 1152 + 2 * 8 * 4 * 128) * 4;  // 106496 B
    cudaFuncSetAttribute(sgemm_tf32_kernel,
                         cudaFuncAttributeMaxDynamicSharedMemorySize, GEMM_SMEM);

    // Lazily-created side stream + fork/join events (host objects, cached).
    static cudaStream_t s2 = nullptr;
    static cudaEvent_t evFork = nullptr, evJoin = nullptr;
    if (!s2) {
        cudaStreamCreateWithFlags(&s2, cudaStreamNonBlocking);
        cudaEventCreateWithFlags(&evFork, cudaEventDisableTiming);
        cudaEventCreateWithFlags(&evJoin, cudaEventDisableTiming);
    }

    // Fork: CSR chain runs on s2 concurrently with prep+gemm1 on stream 0.
    cudaEventRecord(evFork, 0);
    cudaStreamWaitEvent(s2, evFork, 0);
    zeroc_kernel<<<scanBlocks, 256, 0, s2>>>(cnt, n);
    hist_kernel<<<edgeBlocks, 256, 0, s2>>>(dstp, cnt, e);
    scanA_kernel<<<scanBlocks, 256, 0, s2>>>(cnt, bsum, n);
    scanB_kernel<<<1, 256, 0, s2>>>(bsum, boff, scanBlocks);
    scanC_kernel<<<scanBlocks, 256, 0, s2>>>(cnt, boff, offs, cur, n);
    scatter_kernel<<<edgeBlocks, 256, 0, s2>>>(srcp, dstp, cur, csr, e);
    cudaEventRecord(evJoin, s2);

    // Main stream: weights prep + layer-1 GEMM (independent of CSR).
    prep_kernel<<<148, 256>>>(w1_src, w1_dst, res0_w, w2_src, w2_dst,
                              w3_src, w3_dst, res2_w, att3,
                              w1b, w2b, w3b, att3p);
    sgemm_tf32_kernel<<<dim3(3, rowsB), 256, GEMM_SMEM>>>(x, w1b, g1, n, 384, 100);

    // Join: GAT layer 1 needs both gemm1 output and the CSR.
    cudaStreamWaitEvent(0, evJoin, 0);

    // ----- layer 1 -----
    gat4_kernel<<<gatBlocks, 256>>>(g1, 384, att1, b1,
                                    g1 + 256, 384, res0_b,
                                    bn1_g, bn1_b, bn1_m, bn1_v,
                                    h1, 1, offs, csr, n);

    // ----- layer 2 -----
    sgemm_tf32_kernel<<<dim3(2, rowsB), 256, GEMM_SMEM>>>(h1, w2b, g2, n, 256, 128);
    gat4_kernel<<<gatBlocks, 256>>>(g2, 256, att2, b2,
                                    h1, 128, nullptr,
                                    bn2_g, bn2_b, bn2_m, bn2_v,
                                    h2, 1, offs, csr, n);

    // ----- layer 3 -----
    sgemm_tf32_kernel<<<dim3(2, rowsB), 256, GEMM_SMEM>>>(h2, w3b, g3, n, 160, 128);
    gat1_kernel<<<gatBlocks, 256>>>(g3, att3p, b3, res2_b,
                                    bn3_g, bn3_b, bn3_m, bn3_v,
                                    (float*)d_out, offs, csr, n);
}